// round 1
// baseline (speedup 1.0000x reference)
#include <cuda_runtime.h>

// Problem constants
#define B_   2
#define S_   2048
#define D_   1024
#define NH_  16
#define HD_  64
#define M_   (B_*S_)   // 4096

// Scratch (head-major q/k/v, [B,S,D] ctx)
__device__ float g_q[(size_t)B_*NH_*S_*HD_];
__device__ float g_k[(size_t)B_*NH_*S_*HD_];
__device__ float g_v[(size_t)B_*NH_*S_*HD_];
__device__ float g_ctx[(size_t)M_*D_];

// ---------------------------------------------------------------------------
// GEMM: out = A[M,K] @ W[N,K]^T + bias   (N = K = 1024, M = 4096)
// target 0/1/2 -> write head-major into g_q/g_k/g_v
// target -1    -> A := g_ctx, write plain row-major into outp
// Tile: 128x128x8, 256 threads, 8x8 per thread.
// ---------------------------------------------------------------------------
__global__ void __launch_bounds__(256)
gemm_nt(const float* __restrict__ A, const float* __restrict__ W,
        const float* __restrict__ bias, float* __restrict__ outp, int target)
{
    const int K = D_, N = D_;
    __shared__ float As[8][132];
    __shared__ float Bs[8][132];

    const int tid = threadIdx.x;
    const int tx  = tid & 15;     // n group
    const int ty  = tid >> 4;     // m group
    const int bm  = blockIdx.x * 128;
    const int bn  = blockIdx.y * 128;

    const float* Abase = (target < 0) ? (const float*)g_ctx : A;

    float acc[8][8];
#pragma unroll
    for (int i = 0; i < 8; i++)
#pragma unroll
        for (int j = 0; j < 8; j++) acc[i][j] = 0.f;

    const int lrow = tid >> 1;           // 0..127
    const int lk4  = (tid & 1) * 4;      // 0 or 4
    const float* Ap = Abase + (size_t)(bm + lrow) * K + lk4;
    const float* Wp = W     + (size_t)(bn + lrow) * K + lk4;

    for (int k0 = 0; k0 < K; k0 += 8) {
        float4 av = *(const float4*)(Ap + k0);
        float4 wv = *(const float4*)(Wp + k0);
        As[lk4+0][lrow] = av.x; As[lk4+1][lrow] = av.y;
        As[lk4+2][lrow] = av.z; As[lk4+3][lrow] = av.w;
        Bs[lk4+0][lrow] = wv.x; Bs[lk4+1][lrow] = wv.y;
        Bs[lk4+2][lrow] = wv.z; Bs[lk4+3][lrow] = wv.w;
        __syncthreads();
#pragma unroll
        for (int kk = 0; kk < 8; kk++) {
            float ar[8], br[8];
            *(float4*)&ar[0] = *(const float4*)&As[kk][ty*8];
            *(float4*)&ar[4] = *(const float4*)&As[kk][ty*8 + 4];
            *(float4*)&br[0] = *(const float4*)&Bs[kk][tx*8];
            *(float4*)&br[4] = *(const float4*)&Bs[kk][tx*8 + 4];
#pragma unroll
            for (int i = 0; i < 8; i++)
#pragma unroll
                for (int j = 0; j < 8; j++)
                    acc[i][j] = fmaf(ar[i], br[j], acc[i][j]);
        }
        __syncthreads();
    }

    float* qkv = (target == 0) ? g_q : (target == 1) ? g_k : g_v;

#pragma unroll
    for (int i = 0; i < 8; i++) {
        int m = bm + ty*8 + i;
        int b = m >> 11;         // / S_
        int s = m & (S_ - 1);
#pragma unroll
        for (int j = 0; j < 8; j += 4) {
            int n = bn + tx*8 + j;
            float4 r;
            r.x = acc[i][j+0] + bias[n+0];
            r.y = acc[i][j+1] + bias[n+1];
            r.z = acc[i][j+2] + bias[n+2];
            r.w = acc[i][j+3] + bias[n+3];
            if (target < 0) {
                *(float4*)&outp[(size_t)m * N + n] = r;
            } else {
                int h  = n >> 6;
                int hd = n & 63;
                *(float4*)&qkv[((size_t)((b*NH_ + h)*S_ + s))*HD_ + hd] = r;
            }
        }
    }
}

// ---------------------------------------------------------------------------
// Fused attention: per (b,h) and 64-row q tile.
// scores tile = Q @ K^T * scale + at + mask  -> streamed to gmem
// online softmax + P @ V accumulate -> g_ctx [B,S,D]
// smem: Q 64x64 + KV 64x64 (XOR-swizzled) + P 64x64 = 48 KB exactly.
// 256 threads, 4x4 per thread on a 64x64 tile.
// ---------------------------------------------------------------------------
__global__ void __launch_bounds__(256)
attn_kernel(const float* __restrict__ at, const float* __restrict__ mask,
            float* __restrict__ scores)
{
    __shared__ float Qs[64][64];
    __shared__ float KVs[64][64];   // swizzled: col' = col ^ (((row>>2)&15)<<2)
    __shared__ float Ps[64][64];

    const int tid = threadIdx.x;
    const int tx  = tid & 15;
    const int ty  = tid >> 4;
    const int bh  = blockIdx.y;          // 0..31
    const int b   = bh >> 4;             // / NH_
    const int h   = bh & 15;
    const int q0  = blockIdx.x * 64;

    const float* qbase = g_q + (size_t)bh * S_ * HD_;
    const float* kbase = g_k + (size_t)bh * S_ * HD_;
    const float* vbase = g_v + (size_t)bh * S_ * HD_;

    // Load Q tile (plain layout, broadcast-read later)
#pragma unroll
    for (int it = 0; it < 4; it++) {
        int idx = tid + it*256;
        int row = idx >> 4, g = idx & 15;
        float4 v = *(const float4*)&qbase[(size_t)(q0+row)*HD_ + g*4];
        *(float4*)&Qs[row][g*4] = v;
    }

    float run_max[4], run_sum[4], accv[4][4];
#pragma unroll
    for (int r = 0; r < 4; r++) {
        run_max[r] = -1e30f; run_sum[r] = 0.f;
#pragma unroll
        for (int c = 0; c < 4; c++) accv[r][c] = 0.f;
    }

    const float scale = 0.125f;   // 1/sqrt(64)
    const int   kswz  = tx * 4;   // swizzle for K-reads (row>>2 == tx)

    // Mask is per-key-column, constant over q rows; reload per j tile.
    for (int j0 = 0; j0 < S_; j0 += 64) {
        __syncthreads();   // prior PV reads of KVs done
        // Load K tile (swizzled)
#pragma unroll
        for (int it = 0; it < 4; it++) {
            int idx = tid + it*256;
            int row = idx >> 4, g = idx & 15;
            float4 v = *(const float4*)&kbase[(size_t)(j0+row)*HD_ + g*4];
            int c0 = (g*4) ^ (((row >> 2) & 15) << 2);
            *(float4*)&KVs[row][c0] = v;
        }
        __syncthreads();

        // s[r][c] = sum_k Qs[ty*4+r][k] * K[tx*4+c][k]
        float sv[4][4];
#pragma unroll
        for (int r = 0; r < 4; r++)
#pragma unroll
            for (int c = 0; c < 4; c++) sv[r][c] = 0.f;

#pragma unroll 8
        for (int kk = 0; kk < 64; kk++) {
            float qr[4], kr[4];
#pragma unroll
            for (int r = 0; r < 4; r++) qr[r] = Qs[ty*4+r][kk];
#pragma unroll
            for (int c = 0; c < 4; c++) kr[c] = KVs[tx*4+c][kk ^ kswz];
#pragma unroll
            for (int r = 0; r < 4; r++)
#pragma unroll
                for (int c = 0; c < 4; c++)
                    sv[r][c] = fmaf(qr[r], kr[c], sv[r][c]);
        }

        // Epilogue: scale + at + mask; stream scores
        float4 m4 = *(const float4*)&mask[(size_t)b*S_ + j0 + tx*4];
#pragma unroll
        for (int r = 0; r < 4; r++) {
            size_t rowoff = ((size_t)bh * S_ + (size_t)(q0 + ty*4 + r)) * S_
                            + j0 + tx*4;
            float4 a4 = *(const float4*)&at[rowoff];
            sv[r][0] = fmaf(sv[r][0], scale, a4.x) + m4.x;
            sv[r][1] = fmaf(sv[r][1], scale, a4.y) + m4.y;
            sv[r][2] = fmaf(sv[r][2], scale, a4.z) + m4.z;
            sv[r][3] = fmaf(sv[r][3], scale, a4.w) + m4.w;
            if (scores) {
                float4 o = make_float4(sv[r][0], sv[r][1], sv[r][2], sv[r][3]);
                *(float4*)&scores[rowoff] = o;
            }
        }

        // Online softmax (row stats across 16-lane groups)
#pragma unroll
        for (int r = 0; r < 4; r++) {
            float tm = fmaxf(fmaxf(sv[r][0], sv[r][1]), fmaxf(sv[r][2], sv[r][3]));
#pragma unroll
            for (int off = 8; off >= 1; off >>= 1)
                tm = fmaxf(tm, __shfl_xor_sync(0xffffffffu, tm, off, 16));
            float nm    = fmaxf(run_max[r], tm);
            float alpha = __expf(run_max[r] - nm);
            float ps = 0.f;
#pragma unroll
            for (int c = 0; c < 4; c++) { sv[r][c] = __expf(sv[r][c] - nm); ps += sv[r][c]; }
#pragma unroll
            for (int off = 8; off >= 1; off >>= 1)
                ps += __shfl_xor_sync(0xffffffffu, ps, off, 16);
            run_sum[r] = run_sum[r] * alpha + ps;
            run_max[r] = nm;
#pragma unroll
            for (int c = 0; c < 4; c++) accv[r][c] *= alpha;
        }

        // Store P tile
#pragma unroll
        for (int r = 0; r < 4; r++)
#pragma unroll
            for (int c = 0; c < 4; c++)
                Ps[ty*4+r][tx*4+c] = sv[r][c];

        __syncthreads();   // K reads + P writes complete
        // Load V tile over KVs (swizzled)
#pragma unroll
        for (int it = 0; it < 4; it++) {
            int idx = tid + it*256;
            int row = idx >> 4, g = idx & 15;
            float4 v = *(const float4*)&vbase[(size_t)(j0+row)*HD_ + g*4];
            int c0 = (g*4) ^ (((row >> 2) & 15) << 2);
            *(float4*)&KVs[row][c0] = v;
        }
        __syncthreads();

        // accv[r][c] += P[ty*4+r][jj] * V[jj][tx*4+c]
#pragma unroll 8
        for (int jj = 0; jj < 64; jj++) {
            float pr[4];
#pragma unroll
            for (int r = 0; r < 4; r++) pr[r] = Ps[ty*4+r][jj];
            int swzj = ((jj >> 2) & 15) << 2;
            float4 vv = *(const float4*)&KVs[jj][(tx*4) ^ swzj];
            float vr[4] = {vv.x, vv.y, vv.z, vv.w};
#pragma unroll
            for (int r = 0; r < 4; r++)
#pragma unroll
                for (int c = 0; c < 4; c++)
                    accv[r][c] = fmaf(pr[r], vr[c], accv[r][c]);
        }
    }

    // ctx -> [B,S,D]
#pragma unroll
    for (int r = 0; r < 4; r++) {
        float inv = 1.f / run_sum[r];
        float4 o;
        o.x = accv[r][0]*inv; o.y = accv[r][1]*inv;
        o.z = accv[r][2]*inv; o.w = accv[r][3]*inv;
        *(float4*)&g_ctx[((size_t)(b*S_ + q0 + ty*4 + r))*D_ + h*HD_ + tx*4] = o;
    }
}

// ---------------------------------------------------------------------------
extern "C" void kernel_launch(void* const* d_in, const int* in_sizes, int n_in,
                              void* d_out, int out_size)
{
    const float* hidden = (const float*)d_in[0];
    const float* mask   = (const float*)d_in[1];
    const float* at     = (const float*)d_in[2];
    const float* Wq     = (const float*)d_in[3];
    const float* bq     = (const float*)d_in[4];
    const float* Wk     = (const float*)d_in[5];
    const float* bk     = (const float*)d_in[6];
    const float* Wv     = (const float*)d_in[7];
    const float* bv     = (const float*)d_in[8];
    const float* Wo     = (const float*)d_in[9];
    const float* bo     = (const float*)d_in[10];

    float* outp = (float*)d_out;
    const int OUT_ELEMS = 4194304;            // B*S*D
    // scores follow out in the flattened tuple (if the harness sized it so)
    float* scores = (out_size >= OUT_ELEMS + 1) ? (outp + OUT_ELEMS) : nullptr;
    if (out_size < OUT_ELEMS + 1) scores = nullptr;

    dim3 gg(M_/128, D_/128);     // 32 x 8
    gemm_nt<<<gg, 256>>>(hidden, Wq, bq, nullptr, 0);
    gemm_nt<<<gg, 256>>>(hidden, Wk, bk, nullptr, 1);
    gemm_nt<<<gg, 256>>>(hidden, Wv, bv, nullptr, 2);

    dim3 ga(S_/64, B_*NH_);      // 32 x 32
    attn_kernel<<<ga, 256>>>(at, mask, scores);

    gemm_nt<<<gg, 256>>>(nullptr, Wo, bo, outp, -1);
}

// round 6
// speedup vs baseline: 1.3903x; 1.3903x over previous
#include <cuda_runtime.h>
#include <cuda_bf16.h>
#include <cstdint>

// Problem constants
#define B_   2
#define S_   2048
#define D_   1024
#define NH_  16
#define HD_  64
#define M_   (B_*S_)   // 4096

// ---------------------------------------------------------------------------
// Scratch
// ---------------------------------------------------------------------------
__device__ float g_q[(size_t)B_*NH_*S_*HD_];
__device__ float g_k[(size_t)B_*NH_*S_*HD_];
__device__ float g_v[(size_t)B_*NH_*S_*HD_];
__device__ float g_ctx[(size_t)M_*D_];

__device__ __nv_bfloat16 g_hid_h[(size_t)M_*D_];
__device__ __nv_bfloat16 g_hid_l[(size_t)M_*D_];
__device__ __nv_bfloat16 g_ctx_h[(size_t)M_*D_];
__device__ __nv_bfloat16 g_ctx_l[(size_t)M_*D_];
__device__ __nv_bfloat16 g_w_h[4][(size_t)D_*D_];
__device__ __nv_bfloat16 g_w_l[4][(size_t)D_*D_];

// ---------------------------------------------------------------------------
// helpers
// ---------------------------------------------------------------------------
__device__ __forceinline__ uint32_t cvta_smem(const void* p) {
    uint32_t a;
    asm("{ .reg .u64 t; cvta.to.shared.u64 t, %1; cvt.u32.u64 %0, t; }"
        : "=r"(a) : "l"(p));
    return a;
}
__device__ __forceinline__ void cp_async16(uint32_t s, const void* g) {
    asm volatile("cp.async.cg.shared.global [%0], [%1], 16;"
                 :: "r"(s), "l"(g) : "memory");
}
__device__ __forceinline__ void ldsm_x4(uint32_t (&r)[4], uint32_t addr) {
    asm volatile("ldmatrix.sync.aligned.m8n8.x4.shared.b16 {%0,%1,%2,%3}, [%4];"
                 : "=r"(r[0]), "=r"(r[1]), "=r"(r[2]), "=r"(r[3]) : "r"(addr));
}
__device__ __forceinline__ void mma_bf16(float (&c)[4], const uint32_t (&a)[4],
                                         uint32_t b0, uint32_t b1) {
    asm volatile("mma.sync.aligned.m16n8k16.row.col.f32.bf16.bf16.f32 "
                 "{%0,%1,%2,%3}, {%4,%5,%6,%7}, {%8,%9}, {%0,%1,%2,%3};"
                 : "+f"(c[0]), "+f"(c[1]), "+f"(c[2]), "+f"(c[3])
                 : "r"(a[0]), "r"(a[1]), "r"(a[2]), "r"(a[3]),
                   "r"(b0), "r"(b1));
}

// ---------------------------------------------------------------------------
// fp32 -> bf16 hi/lo split (vectorized by 4)
// ---------------------------------------------------------------------------
__global__ void __launch_bounds__(256)
split_kernel(const float* __restrict__ in, __nv_bfloat16* __restrict__ hi,
             __nv_bfloat16* __restrict__ lo, int n4)
{
    int i = blockIdx.x * blockDim.x + threadIdx.x;
    if (i >= n4) return;
    float4 v = ((const float4*)in)[i];
    __nv_bfloat16 h0 = __float2bfloat16(v.x);
    __nv_bfloat16 h1 = __float2bfloat16(v.y);
    __nv_bfloat16 h2 = __float2bfloat16(v.z);
    __nv_bfloat16 h3 = __float2bfloat16(v.w);
    __nv_bfloat16 l0 = __float2bfloat16(v.x - __bfloat162float(h0));
    __nv_bfloat16 l1 = __float2bfloat16(v.y - __bfloat162float(h1));
    __nv_bfloat16 l2 = __float2bfloat16(v.z - __bfloat162float(h2));
    __nv_bfloat16 l3 = __float2bfloat16(v.w - __bfloat162float(h3));
    ((__nv_bfloat162*)hi)[2*i]   = __nv_bfloat162(h0, h1);
    ((__nv_bfloat162*)hi)[2*i+1] = __nv_bfloat162(h2, h3);
    ((__nv_bfloat162*)lo)[2*i]   = __nv_bfloat162(l0, l1);
    ((__nv_bfloat162*)lo)[2*i+1] = __nv_bfloat162(l2, l3);
}

// ---------------------------------------------------------------------------
// HMMA split-precision bf16 GEMM:
//   out[M,N] = A[M,K] @ W[N,K]^T + bias   via Ah*Bh + Ah*Bl + Al*Bh
// CTA tile 128x128, 8 warps (4x2), warp tile 32x64.
// K chunks of 32, NKC = 32 chunks (FIX: was 16 -> only half of K summed),
// cp.async double-buffered.
// ---------------------------------------------------------------------------
#define KC      32
#define NKC     (D_/KC)                  // 32 chunks  <-- the fix
#define AST     40                       // padded row stride (bf16)
#define ROWB    (AST*2)                  // 80 bytes
#define TILE_B  (128*ROWB)               // 10240 bytes
#define STAGE_B (4*TILE_B)               // 40960 bytes
#define GSMEM   (2*STAGE_B)              // 81920 bytes

__global__ void __launch_bounds__(256)
gemm_mma(const __nv_bfloat16* __restrict__ Ah, const __nv_bfloat16* __restrict__ Al,
         const __nv_bfloat16* __restrict__ Bh, const __nv_bfloat16* __restrict__ Bl,
         const float* __restrict__ bias, float* __restrict__ outp, int mode)
{
    extern __shared__ unsigned char smem_raw[];
    const uint32_t sbase = cvta_smem(smem_raw);

    const int tid  = threadIdx.x;
    const int wid  = tid >> 5;
    const int lane = tid & 31;
    const int wm   = wid & 3;            // warp M index (x32)
    const int wn   = wid >> 2;           // warp N index (x64)
    const int bm   = blockIdx.x * 128;
    const int bn   = blockIdx.y * 128;

    const __nv_bfloat16* srcs[4] = { Ah + (size_t)bm * D_, Al + (size_t)bm * D_,
                                     Bh + (size_t)bn * D_, Bl + (size_t)bn * D_ };

    float acc[2][8][4];
#pragma unroll
    for (int mt = 0; mt < 2; mt++)
#pragma unroll
        for (int nt = 0; nt < 8; nt++)
#pragma unroll
            for (int i = 0; i < 4; i++) acc[mt][nt][i] = 0.f;

#define LOAD_STAGE(kc, stg)                                                   \
    do {                                                                      \
        uint32_t sb_ = sbase + (stg) * STAGE_B;                               \
        int k0_ = (kc) * KC;                                                  \
        _Pragma("unroll")                                                     \
        for (int it = 0; it < 8; it++) {                                      \
            int idx  = tid + it * 256;                                        \
            int tile = idx >> 9;                                              \
            int rem  = idx & 511;                                             \
            int row  = rem >> 2;                                              \
            int q    = rem & 3;                                               \
            cp_async16(sb_ + tile * TILE_B + row * ROWB + q * 16,             \
                       srcs[tile] + (size_t)row * D_ + k0_ + q * 8);          \
        }                                                                     \
        asm volatile("cp.async.commit_group;" ::: "memory");                  \
    } while (0)

    LOAD_STAGE(0, 0);

    for (int kc = 0; kc < NKC; kc++) {
        if (kc + 1 < NKC) {
            LOAD_STAGE(kc + 1, (kc + 1) & 1);
            asm volatile("cp.async.wait_group 1;" ::: "memory");
        } else {
            asm volatile("cp.async.wait_group 0;" ::: "memory");
        }
        __syncthreads();

        const uint32_t st = sbase + (kc & 1) * STAGE_B;
        const uint32_t sAh = st + 0 * TILE_B;
        const uint32_t sAl = st + 1 * TILE_B;
        const uint32_t sBh = st + 2 * TILE_B;
        const uint32_t sBl = st + 3 * TILE_B;

#pragma unroll
        for (int ks = 0; ks < 2; ks++) {
            const int kofs = ks * 16;
            // A fragments (2 m16 tiles, hi+lo)
            uint32_t ah[2][4], al[2][4];
            {
                int arow = wm * 32 + (lane & 15);
                int acol = ((lane >> 4) << 3) + kofs;
#pragma unroll
                for (int mt = 0; mt < 2; mt++) {
                    uint32_t off = (uint32_t)(arow + mt * 16) * ROWB + acol * 2;
                    ldsm_x4(ah[mt], sAh + off);
                    ldsm_x4(al[mt], sAl + off);
                }
            }
            // B fragments (8 n8 tiles, hi+lo)
            uint32_t bh[8][2], bl[8][2];
            {
                int brow = wn * 64 + ((lane >> 4) << 3) + (lane & 7);
                int bcol = (((lane >> 3) & 1) << 3) + kofs;
#pragma unroll
                for (int p = 0; p < 4; p++) {
                    uint32_t off = (uint32_t)(brow + p * 16) * ROWB + bcol * 2;
                    uint32_t r[4];
                    ldsm_x4(r, sBh + off);
                    bh[2*p][0] = r[0]; bh[2*p][1] = r[1];
                    bh[2*p+1][0] = r[2]; bh[2*p+1][1] = r[3];
                    ldsm_x4(r, sBl + off);
                    bl[2*p][0] = r[0]; bl[2*p][1] = r[1];
                    bl[2*p+1][0] = r[2]; bl[2*p+1][1] = r[3];
                }
            }
            // 3-pass split-precision MMA
#pragma unroll
            for (int mt = 0; mt < 2; mt++)
#pragma unroll
                for (int nt = 0; nt < 8; nt++) {
                    mma_bf16(acc[mt][nt], ah[mt], bh[nt][0], bh[nt][1]);
                    mma_bf16(acc[mt][nt], ah[mt], bl[nt][0], bl[nt][1]);
                    mma_bf16(acc[mt][nt], al[mt], bh[nt][0], bh[nt][1]);
                }
        }
        __syncthreads();
    }

    // ---- epilogue ----
    const int qr = lane >> 2;            // 0..7
    const int qc = (lane & 3) * 2;       // 0,2,4,6
    float* qkv = (mode == 0) ? g_q : (mode == 1) ? g_k : g_v;

#pragma unroll
    for (int mt = 0; mt < 2; mt++) {
#pragma unroll
        for (int half = 0; half < 2; half++) {
            int m = bm + wm * 32 + mt * 16 + qr + half * 8;
            int b = m >> 11;
            int s = m & (S_ - 1);
#pragma unroll
            for (int nt = 0; nt < 8; nt++) {
                int n = bn + wn * 64 + nt * 8 + qc;
                float2 o;
                o.x = acc[mt][nt][2*half + 0] + bias[n + 0];
                o.y = acc[mt][nt][2*half + 1] + bias[n + 1];
                if (mode == 3) {
                    *(float2*)&outp[(size_t)m * D_ + n] = o;
                } else {
                    int h  = n >> 6;
                    int hd = n & 63;
                    *(float2*)&qkv[((size_t)((b*NH_ + h)*S_ + s))*HD_ + hd] = o;
                }
            }
        }
    }
}

// ---------------------------------------------------------------------------
// Fused fp32 attention (unchanged, known correct)
// ---------------------------------------------------------------------------
__global__ void __launch_bounds__(256)
attn_kernel(const float* __restrict__ at, const float* __restrict__ mask,
            float* __restrict__ scores)
{
    __shared__ float Qs[64][64];
    __shared__ float KVs[64][64];
    __shared__ float Ps[64][64];

    const int tid = threadIdx.x;
    const int tx  = tid & 15;
    const int ty  = tid >> 4;
    const int bh  = blockIdx.y;
    const int b   = bh >> 4;
    const int h   = bh & 15;
    const int q0  = blockIdx.x * 64;

    const float* qbase = g_q + (size_t)bh * S_ * HD_;
    const float* kbase = g_k + (size_t)bh * S_ * HD_;
    const float* vbase = g_v + (size_t)bh * S_ * HD_;

#pragma unroll
    for (int it = 0; it < 4; it++) {
        int idx = tid + it*256;
        int row = idx >> 4, g = idx & 15;
        float4 v = *(const float4*)&qbase[(size_t)(q0+row)*HD_ + g*4];
        *(float4*)&Qs[row][g*4] = v;
    }

    float run_max[4], run_sum[4], accv[4][4];
#pragma unroll
    for (int r = 0; r < 4; r++) {
        run_max[r] = -1e30f; run_sum[r] = 0.f;
#pragma unroll
        for (int c = 0; c < 4; c++) accv[r][c] = 0.f;
    }

    const float scale = 0.125f;
    const int   kswz  = tx * 4;

    for (int j0 = 0; j0 < S_; j0 += 64) {
        __syncthreads();
#pragma unroll
        for (int it = 0; it < 4; it++) {
            int idx = tid + it*256;
            int row = idx >> 4, g = idx & 15;
            float4 v = *(const float4*)&kbase[(size_t)(j0+row)*HD_ + g*4];
            int c0 = (g*4) ^ (((row >> 2) & 15) << 2);
            *(float4*)&KVs[row][c0] = v;
        }
        __syncthreads();

        float sv[4][4];
#pragma unroll
        for (int r = 0; r < 4; r++)
#pragma unroll
            for (int c = 0; c < 4; c++) sv[r][c] = 0.f;

#pragma unroll 8
        for (int kk = 0; kk < 64; kk++) {
            float qr[4], kr[4];
#pragma unroll
            for (int r = 0; r < 4; r++) qr[r] = Qs[ty*4+r][kk];
#pragma unroll
            for (int c = 0; c < 4; c++) kr[c] = KVs[tx*4+c][kk ^ kswz];
#pragma unroll
            for (int r = 0; r < 4; r++)
#pragma unroll
                for (int c = 0; c < 4; c++)
                    sv[r][c] = fmaf(qr[r], kr[c], sv[r][c]);
        }

        float4 m4 = *(const float4*)&mask[(size_t)b*S_ + j0 + tx*4];
#pragma unroll
        for (int r = 0; r < 4; r++) {
            size_t rowoff = ((size_t)bh * S_ + (size_t)(q0 + ty*4 + r)) * S_
                            + j0 + tx*4;
            float4 a4 = *(const float4*)&at[rowoff];
            sv[r][0] = fmaf(sv[r][0], scale, a4.x) + m4.x;
            sv[r][1] = fmaf(sv[r][1], scale, a4.y) + m4.y;
            sv[r][2] = fmaf(sv[r][2], scale, a4.z) + m4.z;
            sv[r][3] = fmaf(sv[r][3], scale, a4.w) + m4.w;
            if (scores) {
                float4 o = make_float4(sv[r][0], sv[r][1], sv[r][2], sv[r][3]);
                *(float4*)&scores[rowoff] = o;
            }
        }

#pragma unroll
        for (int r = 0; r < 4; r++) {
            float tm = fmaxf(fmaxf(sv[r][0], sv[r][1]), fmaxf(sv[r][2], sv[r][3]));
#pragma unroll
            for (int off = 8; off >= 1; off >>= 1)
                tm = fmaxf(tm, __shfl_xor_sync(0xffffffffu, tm, off, 16));
            float nm    = fmaxf(run_max[r], tm);
            float alpha = __expf(run_max[r] - nm);
            float ps = 0.f;
#pragma unroll
            for (int c = 0; c < 4; c++) { sv[r][c] = __expf(sv[r][c] - nm); ps += sv[r][c]; }
#pragma unroll
            for (int off = 8; off >= 1; off >>= 1)
                ps += __shfl_xor_sync(0xffffffffu, ps, off, 16);
            run_sum[r] = run_sum[r] * alpha + ps;
            run_max[r] = nm;
#pragma unroll
            for (int c = 0; c < 4; c++) accv[r][c] *= alpha;
        }

#pragma unroll
        for (int r = 0; r < 4; r++)
#pragma unroll
            for (int c = 0; c < 4; c++)
                Ps[ty*4+r][tx*4+c] = sv[r][c];

        __syncthreads();
#pragma unroll
        for (int it = 0; it < 4; it++) {
            int idx = tid + it*256;
            int row = idx >> 4, g = idx & 15;
            float4 v = *(const float4*)&vbase[(size_t)(j0+row)*HD_ + g*4];
            int c0 = (g*4) ^ (((row >> 2) & 15) << 2);
            *(float4*)&KVs[row][c0] = v;
        }
        __syncthreads();

#pragma unroll 8
        for (int jj = 0; jj < 64; jj++) {
            float pr[4];
#pragma unroll
            for (int r = 0; r < 4; r++) pr[r] = Ps[ty*4+r][jj];
            int swzj = ((jj >> 2) & 15) << 2;
            float4 vv = *(const float4*)&KVs[jj][(tx*4) ^ swzj];
            float vr[4] = {vv.x, vv.y, vv.z, vv.w};
#pragma unroll
            for (int r = 0; r < 4; r++)
#pragma unroll
                for (int c = 0; c < 4; c++)
                    accv[r][c] = fmaf(pr[r], vr[c], accv[r][c]);
        }
    }

#pragma unroll
    for (int r = 0; r < 4; r++) {
        float inv = 1.f / run_sum[r];
        float4 o;
        o.x = accv[r][0]*inv; o.y = accv[r][1]*inv;
        o.z = accv[r][2]*inv; o.w = accv[r][3]*inv;
        *(float4*)&g_ctx[((size_t)(b*S_ + q0 + ty*4 + r))*D_ + h*HD_ + tx*4] = o;
    }
}

// ---------------------------------------------------------------------------
extern "C" void kernel_launch(void* const* d_in, const int* in_sizes, int n_in,
                              void* d_out, int out_size)
{
    const float* hidden = (const float*)d_in[0];
    const float* mask   = (const float*)d_in[1];
    const float* at     = (const float*)d_in[2];
    const float* Wq     = (const float*)d_in[3];
    const float* bq     = (const float*)d_in[4];
    const float* Wk     = (const float*)d_in[5];
    const float* bk     = (const float*)d_in[6];
    const float* Wv     = (const float*)d_in[7];
    const float* bv     = (const float*)d_in[8];
    const float* Wo     = (const float*)d_in[9];
    const float* bo     = (const float*)d_in[10];

    float* outp = (float*)d_out;
    const int OUT_ELEMS = 4194304;            // B*S*D
    float* scores = (out_size >= OUT_ELEMS + 1) ? (outp + OUT_ELEMS) : nullptr;

    cudaFuncSetAttribute(gemm_mma, cudaFuncAttributeMaxDynamicSharedMemorySize,
                         GSMEM);

    __nv_bfloat16 *hid_h, *hid_l, *ctx_h, *ctx_l, *w_h[4], *w_l[4];
    cudaGetSymbolAddress((void**)&hid_h, g_hid_h);
    cudaGetSymbolAddress((void**)&hid_l, g_hid_l);
    cudaGetSymbolAddress((void**)&ctx_h, g_ctx_h);
    cudaGetSymbolAddress((void**)&ctx_l, g_ctx_l);
    {
        __nv_bfloat16* base_h; __nv_bfloat16* base_l;
        cudaGetSymbolAddress((void**)&base_h, g_w_h);
        cudaGetSymbolAddress((void**)&base_l, g_w_l);
        for (int i = 0; i < 4; i++) {
            w_h[i] = base_h + (size_t)i * D_ * D_;
            w_l[i] = base_l + (size_t)i * D_ * D_;
        }
    }
    float* ctx_f;
    cudaGetSymbolAddress((void**)&ctx_f, g_ctx);

    // 1) split fp32 -> bf16 hi/lo
    const int n4_hid = M_ * D_ / 4;
    const int n4_w   = D_ * D_ / 4;
    split_kernel<<<(n4_hid + 255)/256, 256>>>(hidden, hid_h, hid_l, n4_hid);
    split_kernel<<<(n4_w   + 255)/256, 256>>>(Wq, w_h[0], w_l[0], n4_w);
    split_kernel<<<(n4_w   + 255)/256, 256>>>(Wk, w_h[1], w_l[1], n4_w);
    split_kernel<<<(n4_w   + 255)/256, 256>>>(Wv, w_h[2], w_l[2], n4_w);
    split_kernel<<<(n4_w   + 255)/256, 256>>>(Wo, w_h[3], w_l[3], n4_w);

    // 2) QKV projections (HMMA)
    dim3 gg(M_/128, D_/128);     // 32 x 8
    gemm_mma<<<gg, 256, GSMEM>>>(hid_h, hid_l, w_h[0], w_l[0], bq, nullptr, 0);
    gemm_mma<<<gg, 256, GSMEM>>>(hid_h, hid_l, w_h[1], w_l[1], bk, nullptr, 1);
    gemm_mma<<<gg, 256, GSMEM>>>(hid_h, hid_l, w_h[2], w_l[2], bv, nullptr, 2);

    // 3) attention (fp32 SIMT)
    dim3 ga(S_/64, B_*NH_);      // 32 x 32
    attn_kernel<<<ga, 256>>>(at, mask, scores);

    // 4) ctx split + O projection (HMMA)
    split_kernel<<<(n4_hid + 255)/256, 256>>>(ctx_f, ctx_h, ctx_l, n4_hid);
    gemm_mma<<<gg, 256, GSMEM>>>(ctx_h, ctx_l, w_h[3], w_l[3], bo, outp, 3);
}

// round 7
// speedup vs baseline: 2.1449x; 1.5428x over previous
#include <cuda_runtime.h>
#include <cuda_bf16.h>
#include <cstdint>

// Problem constants
#define B_   2
#define S_   2048
#define D_   1024
#define NH_  16
#define HD_  64
#define M_   (B_*S_)   // 4096

// ---------------------------------------------------------------------------
// Scratch (bf16 hi/lo everywhere; no fp32 round-trips)
// ---------------------------------------------------------------------------
__device__ __nv_bfloat16 g_qh[(size_t)B_*NH_*S_*HD_];
__device__ __nv_bfloat16 g_ql[(size_t)B_*NH_*S_*HD_];
__device__ __nv_bfloat16 g_kh[(size_t)B_*NH_*S_*HD_];
__device__ __nv_bfloat16 g_kl[(size_t)B_*NH_*S_*HD_];
__device__ __nv_bfloat16 g_vh[(size_t)B_*NH_*S_*HD_];
__device__ __nv_bfloat16 g_vl[(size_t)B_*NH_*S_*HD_];
__device__ __nv_bfloat16 g_ctx_h[(size_t)M_*D_];
__device__ __nv_bfloat16 g_ctx_l[(size_t)M_*D_];
__device__ __nv_bfloat16 g_hid_h[(size_t)M_*D_];
__device__ __nv_bfloat16 g_hid_l[(size_t)M_*D_];
__device__ __nv_bfloat16 g_w_h[4][(size_t)D_*D_];
__device__ __nv_bfloat16 g_w_l[4][(size_t)D_*D_];

// ---------------------------------------------------------------------------
// helpers
// ---------------------------------------------------------------------------
__device__ __forceinline__ uint32_t cvta_smem(const void* p) {
    uint32_t a;
    asm("{ .reg .u64 t; cvta.to.shared.u64 t, %1; cvt.u32.u64 %0, t; }"
        : "=r"(a) : "l"(p));
    return a;
}
__device__ __forceinline__ void cp_async16(uint32_t s, const void* g) {
    asm volatile("cp.async.cg.shared.global [%0], [%1], 16;"
                 :: "r"(s), "l"(g) : "memory");
}
__device__ __forceinline__ void ldsm_x4(uint32_t (&r)[4], uint32_t addr) {
    asm volatile("ldmatrix.sync.aligned.m8n8.x4.shared.b16 {%0,%1,%2,%3}, [%4];"
                 : "=r"(r[0]), "=r"(r[1]), "=r"(r[2]), "=r"(r[3]) : "r"(addr));
}
__device__ __forceinline__ void ldsm_x4_t(uint32_t (&r)[4], uint32_t addr) {
    asm volatile("ldmatrix.sync.aligned.m8n8.x4.trans.shared.b16 {%0,%1,%2,%3}, [%4];"
                 : "=r"(r[0]), "=r"(r[1]), "=r"(r[2]), "=r"(r[3]) : "r"(addr));
}
__device__ __forceinline__ void mma_bf16(float (&c)[4], const uint32_t (&a)[4],
                                         uint32_t b0, uint32_t b1) {
    asm volatile("mma.sync.aligned.m16n8k16.row.col.f32.bf16.bf16.f32 "
                 "{%0,%1,%2,%3}, {%4,%5,%6,%7}, {%8,%9}, {%0,%1,%2,%3};"
                 : "+f"(c[0]), "+f"(c[1]), "+f"(c[2]), "+f"(c[3])
                 : "r"(a[0]), "r"(a[1]), "r"(a[2]), "r"(a[3]),
                   "r"(b0), "r"(b1));
}
// pack fp32 pair -> bf16 hi pair, residual lo pair
__device__ __forceinline__ uint32_t pack_hl(float x, float y, uint32_t& lo) {
    __nv_bfloat162 h = __floats2bfloat162_rn(x, y);
    float rx = x - __bfloat162float(h.x);
    float ry = y - __bfloat162float(h.y);
    __nv_bfloat162 l = __floats2bfloat162_rn(rx, ry);
    lo = *reinterpret_cast<uint32_t*>(&l);
    return *reinterpret_cast<uint32_t*>(&h);
}

// ---------------------------------------------------------------------------
// fp32 -> bf16 hi/lo split
// ---------------------------------------------------------------------------
__global__ void __launch_bounds__(256)
split_kernel(const float* __restrict__ in, __nv_bfloat16* __restrict__ hi,
             __nv_bfloat16* __restrict__ lo, int n4)
{
    int i = blockIdx.x * blockDim.x + threadIdx.x;
    if (i >= n4) return;
    float4 v = ((const float4*)in)[i];
    uint32_t l0, l1;
    uint32_t h0 = pack_hl(v.x, v.y, l0);
    uint32_t h1 = pack_hl(v.z, v.w, l1);
    ((uint32_t*)hi)[2*i]   = h0;
    ((uint32_t*)hi)[2*i+1] = h1;
    ((uint32_t*)lo)[2*i]   = l0;
    ((uint32_t*)lo)[2*i+1] = l1;
}

// ---------------------------------------------------------------------------
// HMMA split-precision bf16 GEMM (validated R6).
// modes 0/1/2: write bf16 hi/lo head-major to g_{q,k,v}{h,l}.
// mode 3: fp32 row-major to outp.
// ---------------------------------------------------------------------------
#define KC      32
#define NKC     (D_/KC)                  // 32 chunks
#define AST     40
#define ROWB    (AST*2)                  // 80 bytes
#define TILE_B  (128*ROWB)
#define STAGE_B (4*TILE_B)
#define GSMEM   (2*STAGE_B)

__global__ void __launch_bounds__(256)
gemm_mma(const __nv_bfloat16* __restrict__ Ah, const __nv_bfloat16* __restrict__ Al,
         const __nv_bfloat16* __restrict__ Bh, const __nv_bfloat16* __restrict__ Bl,
         const float* __restrict__ bias, float* __restrict__ outp, int mode)
{
    extern __shared__ unsigned char smem_raw[];
    const uint32_t sbase = cvta_smem(smem_raw);

    const int tid  = threadIdx.x;
    const int wid  = tid >> 5;
    const int lane = tid & 31;
    const int wm   = wid & 3;
    const int wn   = wid >> 2;
    const int bm   = blockIdx.x * 128;
    const int bn   = blockIdx.y * 128;

    const __nv_bfloat16* srcs[4] = { Ah + (size_t)bm * D_, Al + (size_t)bm * D_,
                                     Bh + (size_t)bn * D_, Bl + (size_t)bn * D_ };

    float acc[2][8][4];
#pragma unroll
    for (int mt = 0; mt < 2; mt++)
#pragma unroll
        for (int nt = 0; nt < 8; nt++)
#pragma unroll
            for (int i = 0; i < 4; i++) acc[mt][nt][i] = 0.f;

#define LOAD_STAGE(kc, stg)                                                   \
    do {                                                                      \
        uint32_t sb_ = sbase + (stg) * STAGE_B;                               \
        int k0_ = (kc) * KC;                                                  \
        _Pragma("unroll")                                                     \
        for (int it = 0; it < 8; it++) {                                      \
            int idx  = tid + it * 256;                                        \
            int tile = idx >> 9;                                              \
            int rem  = idx & 511;                                             \
            int row  = rem >> 2;                                              \
            int q    = rem & 3;                                               \
            cp_async16(sb_ + tile * TILE_B + row * ROWB + q * 16,             \
                       srcs[tile] + (size_t)row * D_ + k0_ + q * 8);          \
        }                                                                     \
        asm volatile("cp.async.commit_group;" ::: "memory");                  \
    } while (0)

    LOAD_STAGE(0, 0);

    for (int kc = 0; kc < NKC; kc++) {
        if (kc + 1 < NKC) {
            LOAD_STAGE(kc + 1, (kc + 1) & 1);
            asm volatile("cp.async.wait_group 1;" ::: "memory");
        } else {
            asm volatile("cp.async.wait_group 0;" ::: "memory");
        }
        __syncthreads();

        const uint32_t st = sbase + (kc & 1) * STAGE_B;
        const uint32_t sAh = st + 0 * TILE_B;
        const uint32_t sAl = st + 1 * TILE_B;
        const uint32_t sBh = st + 2 * TILE_B;
        const uint32_t sBl = st + 3 * TILE_B;

#pragma unroll
        for (int ks = 0; ks < 2; ks++) {
            const int kofs = ks * 16;
            uint32_t ah[2][4], al[2][4];
            {
                int arow = wm * 32 + (lane & 15);
                int acol = ((lane >> 4) << 3) + kofs;
#pragma unroll
                for (int mt = 0; mt < 2; mt++) {
                    uint32_t off = (uint32_t)(arow + mt * 16) * ROWB + acol * 2;
                    ldsm_x4(ah[mt], sAh + off);
                    ldsm_x4(al[mt], sAl + off);
                }
            }
            uint32_t bh[8][2], bl[8][2];
            {
                int brow = wn * 64 + ((lane >> 4) << 3) + (lane & 7);
                int bcol = (((lane >> 3) & 1) << 3) + kofs;
#pragma unroll
                for (int p = 0; p < 4; p++) {
                    uint32_t off = (uint32_t)(brow + p * 16) * ROWB + bcol * 2;
                    uint32_t r[4];
                    ldsm_x4(r, sBh + off);
                    bh[2*p][0] = r[0]; bh[2*p][1] = r[1];
                    bh[2*p+1][0] = r[2]; bh[2*p+1][1] = r[3];
                    ldsm_x4(r, sBl + off);
                    bl[2*p][0] = r[0]; bl[2*p][1] = r[1];
                    bl[2*p+1][0] = r[2]; bl[2*p+1][1] = r[3];
                }
            }
#pragma unroll
            for (int mt = 0; mt < 2; mt++)
#pragma unroll
                for (int nt = 0; nt < 8; nt++) {
                    mma_bf16(acc[mt][nt], ah[mt], bh[nt][0], bh[nt][1]);
                    mma_bf16(acc[mt][nt], ah[mt], bl[nt][0], bl[nt][1]);
                    mma_bf16(acc[mt][nt], al[mt], bh[nt][0], bh[nt][1]);
                }
        }
        __syncthreads();
    }

    // ---- epilogue ----
    const int qr = lane >> 2;
    const int qc = (lane & 3) * 2;
    __nv_bfloat16* oh = (mode == 0) ? g_qh : (mode == 1) ? g_kh : g_vh;
    __nv_bfloat16* ol = (mode == 0) ? g_ql : (mode == 1) ? g_kl : g_vl;

#pragma unroll
    for (int mt = 0; mt < 2; mt++) {
#pragma unroll
        for (int half = 0; half < 2; half++) {
            int m = bm + wm * 32 + mt * 16 + qr + half * 8;
            int b = m >> 11;
            int s = m & (S_ - 1);
#pragma unroll
            for (int nt = 0; nt < 8; nt++) {
                int n = bn + wn * 64 + nt * 8 + qc;
                float ox = acc[mt][nt][2*half + 0] + bias[n + 0];
                float oy = acc[mt][nt][2*half + 1] + bias[n + 1];
                if (mode == 3) {
                    float2 o = make_float2(ox, oy);
                    *(float2*)&outp[(size_t)m * D_ + n] = o;
                } else {
                    int h  = n >> 6;
                    int hd = n & 63;
                    size_t off = ((size_t)((b*NH_ + h)*S_ + s))*HD_ + hd;
                    uint32_t lo;
                    uint32_t hi = pack_hl(ox, oy, lo);
                    *(uint32_t*)&oh[off] = hi;
                    *(uint32_t*)&ol[off] = lo;
                }
            }
        }
    }
}

// ---------------------------------------------------------------------------
// HMMA flash attention. Block: 128 q-rows x one (b,h). 8 warps, each 16 rows,
// full N=64 per kv tile. 3-pass hi/lo split on both QK^T and PV.
// P fed to PV MMA directly from registers (C-layout == A-layout).
// ---------------------------------------------------------------------------
#define BQ      128
#define BKV     64
#define AST2    72                        // padded bf16 row stride (144B)
#define ROW2B   (AST2*2)
#define QTILE_B (BQ*ROW2B)                // 18432
#define KVT_B   (BKV*ROW2B)               // 9216
#define KVSTG_B (4*KVT_B)                 // 36864
#define ASMEM   (2*QTILE_B + 2*KVSTG_B)   // 110592

__global__ void __launch_bounds__(256)
attn_mma(const float* __restrict__ at, const float* __restrict__ mask,
         float* __restrict__ scores)
{
    extern __shared__ unsigned char smem_raw[];
    const uint32_t sbase = cvta_smem(smem_raw);

    const int tid  = threadIdx.x;
    const int wid  = tid >> 5;
    const int lane = tid & 31;
    const int bh   = blockIdx.y;
    const int b    = bh >> 4;
    const int h    = bh & 15;
    const int q0   = blockIdx.x * BQ;

    const __nv_bfloat16* qh = g_qh + (size_t)bh * S_ * HD_;
    const __nv_bfloat16* ql = g_ql + (size_t)bh * S_ * HD_;
    const __nv_bfloat16* kv_srcs[4] = {
        g_kh + (size_t)bh * S_ * HD_, g_kl + (size_t)bh * S_ * HD_,
        g_vh + (size_t)bh * S_ * HD_, g_vl + (size_t)bh * S_ * HD_ };

    // ---- load Q hi/lo (128 x 64) into smem ----
#pragma unroll
    for (int it = 0; it < 8; it++) {
        int idx  = tid + it * 256;           // 0..2047
        int half = idx >> 10;
        int rem  = idx & 1023;
        int row  = rem >> 3;
        int c    = rem & 7;
        const __nv_bfloat16* src = (half ? ql : qh) + (size_t)(q0 + row) * HD_ + c * 8;
        *(uint4*)(smem_raw + half * QTILE_B + row * ROW2B + c * 16) =
            *(const uint4*)src;
    }

    float cacc[8][4];
#pragma unroll
    for (int nt = 0; nt < 8; nt++)
#pragma unroll
        for (int i = 0; i < 4; i++) cacc[nt][i] = 0.f;
    float run_max0 = -1e30f, run_max1 = -1e30f;
    float run_sum0 = 0.f,    run_sum1 = 0.f;

    const int qr  = lane >> 2;
    const int qc2 = (lane & 3) * 2;
    const int row_l0 = wid * 16 + qr;        // local row (0..127)

#define KV_LOAD(jt, stg)                                                      \
    do {                                                                      \
        uint32_t sb_ = sbase + 2*QTILE_B + (stg) * KVSTG_B;                   \
        int r0_ = (jt) * BKV;                                                 \
        _Pragma("unroll")                                                     \
        for (int it = 0; it < 8; it++) {                                      \
            int idx  = tid + it * 256;                                        \
            int tile = idx >> 9;                                              \
            int rem  = idx & 511;                                             \
            int row  = rem >> 3;                                              \
            int c    = rem & 7;                                               \
            cp_async16(sb_ + tile * KVT_B + row * ROW2B + c * 16,             \
                       kv_srcs[tile] + (size_t)(r0_ + row) * HD_ + c * 8);    \
        }                                                                     \
        asm volatile("cp.async.commit_group;" ::: "memory");                  \
    } while (0)

    KV_LOAD(0, 0);

    const float scale = 0.125f;

    for (int j = 0; j < S_/BKV; j++) {
        if (j + 1 < S_/BKV) {
            KV_LOAD(j + 1, (j + 1) & 1);
            asm volatile("cp.async.wait_group 1;" ::: "memory");
        } else {
            asm volatile("cp.async.wait_group 0;" ::: "memory");
        }
        __syncthreads();

        const uint32_t st  = sbase + 2*QTILE_B + (j & 1) * KVSTG_B;
        const uint32_t sKh = st + 0 * KVT_B;
        const uint32_t sKl = st + 1 * KVT_B;
        const uint32_t sVh = st + 2 * KVT_B;
        const uint32_t sVl = st + 3 * KVT_B;

        // ---- S = Q @ K^T (3-pass) ----
        float sacc[8][4];
#pragma unroll
        for (int nt = 0; nt < 8; nt++)
#pragma unroll
            for (int i = 0; i < 4; i++) sacc[nt][i] = 0.f;

#pragma unroll
        for (int ks = 0; ks < 4; ks++) {
            uint32_t qhf[4], qlf[4];
            {
                uint32_t off = (uint32_t)(wid * 16 + (lane & 15)) * ROW2B
                             + ks * 32 + ((lane >> 4) << 4);
                ldsm_x4(qhf, sbase + off);
                ldsm_x4(qlf, sbase + QTILE_B + off);
            }
#pragma unroll
            for (int np = 0; np < 4; np++) {
                int brow = np * 16 + ((lane >> 4) << 3) + (lane & 7);
                uint32_t off = (uint32_t)brow * ROW2B
                             + (((lane >> 3) & 1) << 4) + ks * 32;
                uint32_t rh[4], rl[4];
                ldsm_x4(rh, sKh + off);
                ldsm_x4(rl, sKl + off);
                mma_bf16(sacc[2*np],   qhf, rh[0], rh[1]);
                mma_bf16(sacc[2*np],   qhf, rl[0], rl[1]);
                mma_bf16(sacc[2*np],   qlf, rh[0], rh[1]);
                mma_bf16(sacc[2*np+1], qhf, rh[2], rh[3]);
                mma_bf16(sacc[2*np+1], qhf, rl[2], rl[3]);
                mma_bf16(sacc[2*np+1], qlf, rh[2], rh[3]);
            }
        }

        // ---- epilogue: scale + at + mask, stream scores, online softmax ----
        const int j0 = j * BKV;
        float rm0 = -1e30f, rm1 = -1e30f;
#pragma unroll
        for (int nt = 0; nt < 8; nt++) {
            int col = j0 + nt * 8 + qc2;
            float2 mk = *(const float2*)&mask[(size_t)b * S_ + col];
            size_t off0 = ((size_t)bh * S_ + (size_t)(q0 + row_l0)) * S_ + col;
            size_t off1 = off0 + (size_t)8 * S_;
            float2 a0 = *(const float2*)&at[off0];
            float2 a1 = *(const float2*)&at[off1];
            sacc[nt][0] = fmaf(sacc[nt][0], scale, a0.x) + mk.x;
            sacc[nt][1] = fmaf(sacc[nt][1], scale, a0.y) + mk.y;
            sacc[nt][2] = fmaf(sacc[nt][2], scale, a1.x) + mk.x;
            sacc[nt][3] = fmaf(sacc[nt][3], scale, a1.y) + mk.y;
            *(float2*)&scores[off0] = make_float2(sacc[nt][0], sacc[nt][1]);
            *(float2*)&scores[off1] = make_float2(sacc[nt][2], sacc[nt][3]);
            rm0 = fmaxf(rm0, fmaxf(sacc[nt][0], sacc[nt][1]));
            rm1 = fmaxf(rm1, fmaxf(sacc[nt][2], sacc[nt][3]));
        }
        rm0 = fmaxf(rm0, __shfl_xor_sync(0xffffffffu, rm0, 1));
        rm0 = fmaxf(rm0, __shfl_xor_sync(0xffffffffu, rm0, 2));
        rm1 = fmaxf(rm1, __shfl_xor_sync(0xffffffffu, rm1, 1));
        rm1 = fmaxf(rm1, __shfl_xor_sync(0xffffffffu, rm1, 2));

        float nm0 = fmaxf(run_max0, rm0);
        float nm1 = fmaxf(run_max1, rm1);
        float alpha0 = __expf(run_max0 - nm0);
        float alpha1 = __expf(run_max1 - nm1);
        run_max0 = nm0; run_max1 = nm1;

        float ps0 = 0.f, ps1 = 0.f;
#pragma unroll
        for (int nt = 0; nt < 8; nt++) {
            sacc[nt][0] = __expf(sacc[nt][0] - nm0);
            sacc[nt][1] = __expf(sacc[nt][1] - nm0);
            sacc[nt][2] = __expf(sacc[nt][2] - nm1);
            sacc[nt][3] = __expf(sacc[nt][3] - nm1);
            ps0 += sacc[nt][0] + sacc[nt][1];
            ps1 += sacc[nt][2] + sacc[nt][3];
        }
        ps0 += __shfl_xor_sync(0xffffffffu, ps0, 1);
        ps0 += __shfl_xor_sync(0xffffffffu, ps0, 2);
        ps1 += __shfl_xor_sync(0xffffffffu, ps1, 1);
        ps1 += __shfl_xor_sync(0xffffffffu, ps1, 2);
        run_sum0 = run_sum0 * alpha0 + ps0;
        run_sum1 = run_sum1 * alpha1 + ps1;

#pragma unroll
        for (int nt = 0; nt < 8; nt++) {
            cacc[nt][0] *= alpha0; cacc[nt][1] *= alpha0;
            cacc[nt][2] *= alpha1; cacc[nt][3] *= alpha1;
        }

        // ---- ctx += P @ V (3-pass; P from registers, V^T via ldmatrix.trans)
#pragma unroll
        for (int kk = 0; kk < 4; kk++) {
            uint32_t pah[4], pal[4];
            pah[0] = pack_hl(sacc[2*kk][0],   sacc[2*kk][1],   pal[0]);
            pah[1] = pack_hl(sacc[2*kk][2],   sacc[2*kk][3],   pal[1]);
            pah[2] = pack_hl(sacc[2*kk+1][0], sacc[2*kk+1][1], pal[2]);
            pah[3] = pack_hl(sacc[2*kk+1][2], sacc[2*kk+1][3], pal[3]);
#pragma unroll
            for (int np = 0; np < 4; np++) {
                uint32_t off = (uint32_t)(kk * 16 + (lane & 15)) * ROW2B
                             + np * 32 + ((lane >> 4) << 4);
                uint32_t vh[4], vl[4];
                ldsm_x4_t(vh, sVh + off);
                ldsm_x4_t(vl, sVl + off);
                mma_bf16(cacc[2*np],   pah, vh[0], vh[1]);
                mma_bf16(cacc[2*np],   pal, vh[0], vh[1]);
                mma_bf16(cacc[2*np],   pah, vl[0], vl[1]);
                mma_bf16(cacc[2*np+1], pah, vh[2], vh[3]);
                mma_bf16(cacc[2*np+1], pal, vh[2], vh[3]);
                mma_bf16(cacc[2*np+1], pah, vl[2], vl[3]);
            }
        }
        __syncthreads();
    }

    // ---- final: ctx hi/lo -> g_ctx_h/l [B,S,D] ----
    float inv0 = 1.f / run_sum0;
    float inv1 = 1.f / run_sum1;
    size_t grow0 = (size_t)b * S_ + (q0 + row_l0);
#pragma unroll
    for (int nt = 0; nt < 8; nt++) {
        int col = h * HD_ + nt * 8 + qc2;
        uint32_t lo;
        uint32_t hi = pack_hl(cacc[nt][0] * inv0, cacc[nt][1] * inv0, lo);
        *(uint32_t*)&g_ctx_h[grow0 * D_ + col] = hi;
        *(uint32_t*)&g_ctx_l[grow0 * D_ + col] = lo;
        hi = pack_hl(cacc[nt][2] * inv1, cacc[nt][3] * inv1, lo);
        *(uint32_t*)&g_ctx_h[(grow0 + 8) * D_ + col] = hi;
        *(uint32_t*)&g_ctx_l[(grow0 + 8) * D_ + col] = lo;
    }
}

// ---------------------------------------------------------------------------
extern "C" void kernel_launch(void* const* d_in, const int* in_sizes, int n_in,
                              void* d_out, int out_size)
{
    const float* hidden = (const float*)d_in[0];
    const float* mask   = (const float*)d_in[1];
    const float* at     = (const float*)d_in[2];
    const float* Wq     = (const float*)d_in[3];
    const float* bq     = (const float*)d_in[4];
    const float* Wk     = (const float*)d_in[5];
    const float* bk     = (const float*)d_in[6];
    const float* Wv     = (const float*)d_in[7];
    const float* bv     = (const float*)d_in[8];
    const float* Wo     = (const float*)d_in[9];
    const float* bo     = (const float*)d_in[10];

    float* outp = (float*)d_out;
    const int OUT_ELEMS = 4194304;            // B*S*D
    float* scores = (out_size >= OUT_ELEMS + 1) ? (outp + OUT_ELEMS) : nullptr;

    cudaFuncSetAttribute(gemm_mma, cudaFuncAttributeMaxDynamicSharedMemorySize,
                         GSMEM);
    cudaFuncSetAttribute(attn_mma, cudaFuncAttributeMaxDynamicSharedMemorySize,
                         ASMEM);

    __nv_bfloat16 *hid_h, *hid_l, *ctx_h, *ctx_l, *w_h[4], *w_l[4];
    cudaGetSymbolAddress((void**)&hid_h, g_hid_h);
    cudaGetSymbolAddress((void**)&hid_l, g_hid_l);
    cudaGetSymbolAddress((void**)&ctx_h, g_ctx_h);
    cudaGetSymbolAddress((void**)&ctx_l, g_ctx_l);
    {
        __nv_bfloat16* base_h; __nv_bfloat16* base_l;
        cudaGetSymbolAddress((void**)&base_h, g_w_h);
        cudaGetSymbolAddress((void**)&base_l, g_w_l);
        for (int i = 0; i < 4; i++) {
            w_h[i] = base_h + (size_t)i * D_ * D_;
            w_l[i] = base_l + (size_t)i * D_ * D_;
        }
    }

    // 1) split fp32 -> bf16 hi/lo
    const int n4_hid = M_ * D_ / 4;
    const int n4_w   = D_ * D_ / 4;
    split_kernel<<<(n4_hid + 255)/256, 256>>>(hidden, hid_h, hid_l, n4_hid);
    split_kernel<<<(n4_w   + 255)/256, 256>>>(Wq, w_h[0], w_l[0], n4_w);
    split_kernel<<<(n4_w   + 255)/256, 256>>>(Wk, w_h[1], w_l[1], n4_w);
    split_kernel<<<(n4_w   + 255)/256, 256>>>(Wv, w_h[2], w_l[2], n4_w);
    split_kernel<<<(n4_w   + 255)/256, 256>>>(Wo, w_h[3], w_l[3], n4_w);

    // 2) QKV projections (HMMA) -> bf16 hi/lo head-major
    dim3 gg(M_/128, D_/128);
    gemm_mma<<<gg, 256, GSMEM>>>(hid_h, hid_l, w_h[0], w_l[0], bq, nullptr, 0);
    gemm_mma<<<gg, 256, GSMEM>>>(hid_h, hid_l, w_h[1], w_l[1], bk, nullptr, 1);
    gemm_mma<<<gg, 256, GSMEM>>>(hid_h, hid_l, w_h[2], w_l[2], bv, nullptr, 2);

    // 3) attention (HMMA flash) -> ctx hi/lo
    dim3 ga(S_/BQ, B_*NH_);              // 16 x 32
    attn_mma<<<ga, 256, ASMEM>>>(at, mask, scores);

    // 4) O projection (HMMA)
    gemm_mma<<<gg, 256, GSMEM>>>(ctx_h, ctx_l, w_h[3], w_l[3], bo, outp, 3);
}

// round 8
// speedup vs baseline: 2.2591x; 1.0532x over previous
#include <cuda_runtime.h>
#include <cuda_bf16.h>
#include <cstdint>

// Problem constants
#define B_   2
#define S_   2048
#define D_   1024
#define NH_  16
#define HD_  64
#define M_   (B_*S_)   // 4096

// ---------------------------------------------------------------------------
// Scratch (bf16 hi/lo everywhere; no fp32 round-trips)
// ---------------------------------------------------------------------------
__device__ __nv_bfloat16 g_qh[(size_t)B_*NH_*S_*HD_];
__device__ __nv_bfloat16 g_ql[(size_t)B_*NH_*S_*HD_];
__device__ __nv_bfloat16 g_kh[(size_t)B_*NH_*S_*HD_];
__device__ __nv_bfloat16 g_kl[(size_t)B_*NH_*S_*HD_];
__device__ __nv_bfloat16 g_vh[(size_t)B_*NH_*S_*HD_];
__device__ __nv_bfloat16 g_vl[(size_t)B_*NH_*S_*HD_];
__device__ __nv_bfloat16 g_ctx_h[(size_t)M_*D_];
__device__ __nv_bfloat16 g_ctx_l[(size_t)M_*D_];
__device__ __nv_bfloat16 g_hid_h[(size_t)M_*D_];
__device__ __nv_bfloat16 g_hid_l[(size_t)M_*D_];
__device__ __nv_bfloat16 g_w_h[4][(size_t)D_*D_];
__device__ __nv_bfloat16 g_w_l[4][(size_t)D_*D_];

// ---------------------------------------------------------------------------
// helpers
// ---------------------------------------------------------------------------
__device__ __forceinline__ uint32_t cvta_smem(const void* p) {
    uint32_t a;
    asm("{ .reg .u64 t; cvta.to.shared.u64 t, %1; cvt.u32.u64 %0, t; }"
        : "=r"(a) : "l"(p));
    return a;
}
__device__ __forceinline__ void cp_async16(uint32_t s, const void* g) {
    asm volatile("cp.async.cg.shared.global [%0], [%1], 16;"
                 :: "r"(s), "l"(g) : "memory");
}
__device__ __forceinline__ void ldsm_x4(uint32_t (&r)[4], uint32_t addr) {
    asm volatile("ldmatrix.sync.aligned.m8n8.x4.shared.b16 {%0,%1,%2,%3}, [%4];"
                 : "=r"(r[0]), "=r"(r[1]), "=r"(r[2]), "=r"(r[3]) : "r"(addr));
}
__device__ __forceinline__ void ldsm_x4_t(uint32_t (&r)[4], uint32_t addr) {
    asm volatile("ldmatrix.sync.aligned.m8n8.x4.trans.shared.b16 {%0,%1,%2,%3}, [%4];"
                 : "=r"(r[0]), "=r"(r[1]), "=r"(r[2]), "=r"(r[3]) : "r"(addr));
}
__device__ __forceinline__ void mma_bf16(float (&c)[4], const uint32_t (&a)[4],
                                         uint32_t b0, uint32_t b1) {
    asm volatile("mma.sync.aligned.m16n8k16.row.col.f32.bf16.bf16.f32 "
                 "{%0,%1,%2,%3}, {%4,%5,%6,%7}, {%8,%9}, {%0,%1,%2,%3};"
                 : "+f"(c[0]), "+f"(c[1]), "+f"(c[2]), "+f"(c[3])
                 : "r"(a[0]), "r"(a[1]), "r"(a[2]), "r"(a[3]),
                   "r"(b0), "r"(b1));
}
__device__ __forceinline__ uint32_t pack_hl(float x, float y, uint32_t& lo) {
    __nv_bfloat162 h = __floats2bfloat162_rn(x, y);
    float rx = x - __bfloat162float(h.x);
    float ry = y - __bfloat162float(h.y);
    __nv_bfloat162 l = __floats2bfloat162_rn(rx, ry);
    lo = *reinterpret_cast<uint32_t*>(&l);
    return *reinterpret_cast<uint32_t*>(&h);
}

// ---------------------------------------------------------------------------
// fp32 -> bf16 hi/lo split
// ---------------------------------------------------------------------------
__global__ void __launch_bounds__(256)
split_kernel(const float* __restrict__ in, __nv_bfloat16* __restrict__ hi,
             __nv_bfloat16* __restrict__ lo, int n4)
{
    int i = blockIdx.x * blockDim.x + threadIdx.x;
    if (i >= n4) return;
    float4 v = ((const float4*)in)[i];
    uint32_t l0, l1;
    uint32_t h0 = pack_hl(v.x, v.y, l0);
    uint32_t h1 = pack_hl(v.z, v.w, l1);
    ((uint32_t*)hi)[2*i]   = h0;
    ((uint32_t*)hi)[2*i+1] = h1;
    ((uint32_t*)lo)[2*i]   = l0;
    ((uint32_t*)lo)[2*i+1] = l1;
}

// ---------------------------------------------------------------------------
// HMMA split-precision bf16 GEMM (validated R6/R7)
// ---------------------------------------------------------------------------
#define KC      32
#define NKC     (D_/KC)
#define AST     40
#define ROWB    (AST*2)
#define TILE_B  (128*ROWB)
#define STAGE_B (4*TILE_B)
#define GSMEM   (2*STAGE_B)

__global__ void __launch_bounds__(256)
gemm_mma(const __nv_bfloat16* __restrict__ Ah, const __nv_bfloat16* __restrict__ Al,
         const __nv_bfloat16* __restrict__ Bh, const __nv_bfloat16* __restrict__ Bl,
         const float* __restrict__ bias, float* __restrict__ outp, int mode)
{
    extern __shared__ unsigned char smem_raw[];
    const uint32_t sbase = cvta_smem(smem_raw);

    const int tid  = threadIdx.x;
    const int wid  = tid >> 5;
    const int lane = tid & 31;
    const int wm   = wid & 3;
    const int wn   = wid >> 2;
    const int bm   = blockIdx.x * 128;
    const int bn   = blockIdx.y * 128;

    const __nv_bfloat16* srcs[4] = { Ah + (size_t)bm * D_, Al + (size_t)bm * D_,
                                     Bh + (size_t)bn * D_, Bl + (size_t)bn * D_ };

    float acc[2][8][4];
#pragma unroll
    for (int mt = 0; mt < 2; mt++)
#pragma unroll
        for (int nt = 0; nt < 8; nt++)
#pragma unroll
            for (int i = 0; i < 4; i++) acc[mt][nt][i] = 0.f;

#define LOAD_STAGE(kc, stg)                                                   \
    do {                                                                      \
        uint32_t sb_ = sbase + (stg) * STAGE_B;                               \
        int k0_ = (kc) * KC;                                                  \
        _Pragma("unroll")                                                     \
        for (int it = 0; it < 8; it++) {                                      \
            int idx  = tid + it * 256;                                        \
            int tile = idx >> 9;                                              \
            int rem  = idx & 511;                                             \
            int row  = rem >> 2;                                              \
            int q    = rem & 3;                                               \
            cp_async16(sb_ + tile * TILE_B + row * ROWB + q * 16,             \
                       srcs[tile] + (size_t)row * D_ + k0_ + q * 8);          \
        }                                                                     \
        asm volatile("cp.async.commit_group;" ::: "memory");                  \
    } while (0)

    LOAD_STAGE(0, 0);

    for (int kc = 0; kc < NKC; kc++) {
        if (kc + 1 < NKC) {
            LOAD_STAGE(kc + 1, (kc + 1) & 1);
            asm volatile("cp.async.wait_group 1;" ::: "memory");
        } else {
            asm volatile("cp.async.wait_group 0;" ::: "memory");
        }
        __syncthreads();

        const uint32_t st = sbase + (kc & 1) * STAGE_B;
        const uint32_t sAh = st + 0 * TILE_B;
        const uint32_t sAl = st + 1 * TILE_B;
        const uint32_t sBh = st + 2 * TILE_B;
        const uint32_t sBl = st + 3 * TILE_B;

#pragma unroll
        for (int ks = 0; ks < 2; ks++) {
            const int kofs = ks * 16;
            uint32_t ah[2][4], al[2][4];
            {
                int arow = wm * 32 + (lane & 15);
                int acol = ((lane >> 4) << 3) + kofs;
#pragma unroll
                for (int mt = 0; mt < 2; mt++) {
                    uint32_t off = (uint32_t)(arow + mt * 16) * ROWB + acol * 2;
                    ldsm_x4(ah[mt], sAh + off);
                    ldsm_x4(al[mt], sAl + off);
                }
            }
            uint32_t bh[8][2], bl[8][2];
            {
                int brow = wn * 64 + ((lane >> 4) << 3) + (lane & 7);
                int bcol = (((lane >> 3) & 1) << 3) + kofs;
#pragma unroll
                for (int p = 0; p < 4; p++) {
                    uint32_t off = (uint32_t)(brow + p * 16) * ROWB + bcol * 2;
                    uint32_t r[4];
                    ldsm_x4(r, sBh + off);
                    bh[2*p][0] = r[0]; bh[2*p][1] = r[1];
                    bh[2*p+1][0] = r[2]; bh[2*p+1][1] = r[3];
                    ldsm_x4(r, sBl + off);
                    bl[2*p][0] = r[0]; bl[2*p][1] = r[1];
                    bl[2*p+1][0] = r[2]; bl[2*p+1][1] = r[3];
                }
            }
#pragma unroll
            for (int mt = 0; mt < 2; mt++)
#pragma unroll
                for (int nt = 0; nt < 8; nt++) {
                    mma_bf16(acc[mt][nt], ah[mt], bh[nt][0], bh[nt][1]);
                    mma_bf16(acc[mt][nt], ah[mt], bl[nt][0], bl[nt][1]);
                    mma_bf16(acc[mt][nt], al[mt], bh[nt][0], bh[nt][1]);
                }
        }
        __syncthreads();
    }

    const int qr = lane >> 2;
    const int qc = (lane & 3) * 2;
    __nv_bfloat16* oh = (mode == 0) ? g_qh : (mode == 1) ? g_kh : g_vh;
    __nv_bfloat16* ol = (mode == 0) ? g_ql : (mode == 1) ? g_kl : g_vl;

#pragma unroll
    for (int mt = 0; mt < 2; mt++) {
#pragma unroll
        for (int half = 0; half < 2; half++) {
            int m = bm + wm * 32 + mt * 16 + qr + half * 8;
            int b = m >> 11;
            int s = m & (S_ - 1);
#pragma unroll
            for (int nt = 0; nt < 8; nt++) {
                int n = bn + wn * 64 + nt * 8 + qc;
                float ox = acc[mt][nt][2*half + 0] + bias[n + 0];
                float oy = acc[mt][nt][2*half + 1] + bias[n + 1];
                if (mode == 3) {
                    float2 o = make_float2(ox, oy);
                    *(float2*)&outp[(size_t)m * D_ + n] = o;
                } else {
                    int h  = n >> 6;
                    int hd = n & 63;
                    size_t off = ((size_t)((b*NH_ + h)*S_ + s))*HD_ + hd;
                    uint32_t lo;
                    uint32_t hi = pack_hl(ox, oy, lo);
                    *(uint32_t*)&oh[off] = hi;
                    *(uint32_t*)&ol[off] = lo;
                }
            }
        }
    }
}

// ---------------------------------------------------------------------------
// HMMA flash attention. R8: BQ 128->64, 128 threads (4 warps x 16 rows),
// smem 92.2KB -> 2 CTAs/SM so softmax/epilogue of one CTA overlaps MMA of
// the other. Per-warp fragment code identical to validated R7.
// ---------------------------------------------------------------------------
#define BQ      64
#define ATHREADS 128
#define BKV     64
#define AST2    72
#define ROW2B   (AST2*2)
#define QTILE_B (BQ*ROW2B)                // 9216
#define KVT_B   (BKV*ROW2B)               // 9216
#define KVSTG_B (4*KVT_B)                 // 36864
#define ASMEM   (2*QTILE_B + 2*KVSTG_B)   // 92160

__global__ void __launch_bounds__(ATHREADS)
attn_mma(const float* __restrict__ at, const float* __restrict__ mask,
         float* __restrict__ scores)
{
    extern __shared__ unsigned char smem_raw[];
    const uint32_t sbase = cvta_smem(smem_raw);

    const int tid  = threadIdx.x;
    const int wid  = tid >> 5;
    const int lane = tid & 31;
    const int bh   = blockIdx.y;
    const int b    = bh >> 4;
    const int h    = bh & 15;
    const int q0   = blockIdx.x * BQ;

    const __nv_bfloat16* qh = g_qh + (size_t)bh * S_ * HD_;
    const __nv_bfloat16* ql = g_ql + (size_t)bh * S_ * HD_;
    const __nv_bfloat16* kv_srcs[4] = {
        g_kh + (size_t)bh * S_ * HD_, g_kl + (size_t)bh * S_ * HD_,
        g_vh + (size_t)bh * S_ * HD_, g_vl + (size_t)bh * S_ * HD_ };

    // ---- load Q hi/lo (64 x 64) into smem ----
#pragma unroll
    for (int it = 0; it < 8; it++) {
        int idx  = tid + it * ATHREADS;      // 0..1023
        int half = idx >> 9;
        int rem  = idx & 511;
        int row  = rem >> 3;
        int c    = rem & 7;
        const __nv_bfloat16* src = (half ? ql : qh) + (size_t)(q0 + row) * HD_ + c * 8;
        *(uint4*)(smem_raw + half * QTILE_B + row * ROW2B + c * 16) =
            *(const uint4*)src;
    }

    float cacc[8][4];
#pragma unroll
    for (int nt = 0; nt < 8; nt++)
#pragma unroll
        for (int i = 0; i < 4; i++) cacc[nt][i] = 0.f;
    float run_max0 = -1e30f, run_max1 = -1e30f;
    float run_sum0 = 0.f,    run_sum1 = 0.f;

    const int qr  = lane >> 2;
    const int qc2 = (lane & 3) * 2;
    const int row_l0 = wid * 16 + qr;        // local row (0..63)

#define KV_LOAD(jt, stg)                                                      \
    do {                                                                      \
        uint32_t sb_ = sbase + 2*QTILE_B + (stg) * KVSTG_B;                   \
        int r0_ = (jt) * BKV;                                                 \
        _Pragma("unroll")                                                     \
        for (int it = 0; it < 16; it++) {                                     \
            int idx  = tid + it * ATHREADS;                                   \
            int tile = idx >> 9;                                              \
            int rem  = idx & 511;                                             \
            int row  = rem >> 3;                                              \
            int c    = rem & 7;                                               \
            cp_async16(sb_ + tile * KVT_B + row * ROW2B + c * 16,             \
                       kv_srcs[tile] + (size_t)(r0_ + row) * HD_ + c * 8);    \
        }                                                                     \
        asm volatile("cp.async.commit_group;" ::: "memory");                  \
    } while (0)

    KV_LOAD(0, 0);

    const float scale = 0.125f;

    for (int j = 0; j < S_/BKV; j++) {
        if (j + 1 < S_/BKV) {
            KV_LOAD(j + 1, (j + 1) & 1);
            asm volatile("cp.async.wait_group 1;" ::: "memory");
        } else {
            asm volatile("cp.async.wait_group 0;" ::: "memory");
        }
        __syncthreads();

        const uint32_t st  = sbase + 2*QTILE_B + (j & 1) * KVSTG_B;
        const uint32_t sKh = st + 0 * KVT_B;
        const uint32_t sKl = st + 1 * KVT_B;
        const uint32_t sVh = st + 2 * KVT_B;
        const uint32_t sVl = st + 3 * KVT_B;

        // ---- S = Q @ K^T (3-pass) ----
        float sacc[8][4];
#pragma unroll
        for (int nt = 0; nt < 8; nt++)
#pragma unroll
            for (int i = 0; i < 4; i++) sacc[nt][i] = 0.f;

#pragma unroll
        for (int ks = 0; ks < 4; ks++) {
            uint32_t qhf[4], qlf[4];
            {
                uint32_t off = (uint32_t)(wid * 16 + (lane & 15)) * ROW2B
                             + ks * 32 + ((lane >> 4) << 4);
                ldsm_x4(qhf, sbase + off);
                ldsm_x4(qlf, sbase + QTILE_B + off);
            }
#pragma unroll
            for (int np = 0; np < 4; np++) {
                int brow = np * 16 + ((lane >> 4) << 3) + (lane & 7);
                uint32_t off = (uint32_t)brow * ROW2B
                             + (((lane >> 3) & 1) << 4) + ks * 32;
                uint32_t rh[4], rl[4];
                ldsm_x4(rh, sKh + off);
                ldsm_x4(rl, sKl + off);
                mma_bf16(sacc[2*np],   qhf, rh[0], rh[1]);
                mma_bf16(sacc[2*np],   qhf, rl[0], rl[1]);
                mma_bf16(sacc[2*np],   qlf, rh[0], rh[1]);
                mma_bf16(sacc[2*np+1], qhf, rh[2], rh[3]);
                mma_bf16(sacc[2*np+1], qhf, rl[2], rl[3]);
                mma_bf16(sacc[2*np+1], qlf, rh[2], rh[3]);
            }
        }

        // ---- epilogue: scale + at + mask, stream scores, online softmax ----
        const int j0 = j * BKV;
        float rm0 = -1e30f, rm1 = -1e30f;
#pragma unroll
        for (int nt = 0; nt < 8; nt++) {
            int col = j0 + nt * 8 + qc2;
            float2 mk = *(const float2*)&mask[(size_t)b * S_ + col];
            size_t off0 = ((size_t)bh * S_ + (size_t)(q0 + row_l0)) * S_ + col;
            size_t off1 = off0 + (size_t)8 * S_;
            float2 a0 = *(const float2*)&at[off0];
            float2 a1 = *(const float2*)&at[off1];
            sacc[nt][0] = fmaf(sacc[nt][0], scale, a0.x) + mk.x;
            sacc[nt][1] = fmaf(sacc[nt][1], scale, a0.y) + mk.y;
            sacc[nt][2] = fmaf(sacc[nt][2], scale, a1.x) + mk.x;
            sacc[nt][3] = fmaf(sacc[nt][3], scale, a1.y) + mk.y;
            *(float2*)&scores[off0] = make_float2(sacc[nt][0], sacc[nt][1]);
            *(float2*)&scores[off1] = make_float2(sacc[nt][2], sacc[nt][3]);
            rm0 = fmaxf(rm0, fmaxf(sacc[nt][0], sacc[nt][1]));
            rm1 = fmaxf(rm1, fmaxf(sacc[nt][2], sacc[nt][3]));
        }
        rm0 = fmaxf(rm0, __shfl_xor_sync(0xffffffffu, rm0, 1));
        rm0 = fmaxf(rm0, __shfl_xor_sync(0xffffffffu, rm0, 2));
        rm1 = fmaxf(rm1, __shfl_xor_sync(0xffffffffu, rm1, 1));
        rm1 = fmaxf(rm1, __shfl_xor_sync(0xffffffffu, rm1, 2));

        float nm0 = fmaxf(run_max0, rm0);
        float nm1 = fmaxf(run_max1, rm1);
        float alpha0 = __expf(run_max0 - nm0);
        float alpha1 = __expf(run_max1 - nm1);
        run_max0 = nm0; run_max1 = nm1;

        float ps0 = 0.f, ps1 = 0.f;
#pragma unroll
        for (int nt = 0; nt < 8; nt++) {
            sacc[nt][0] = __expf(sacc[nt][0] - nm0);
            sacc[nt][1] = __expf(sacc[nt][1] - nm0);
            sacc[nt][2] = __expf(sacc[nt][2] - nm1);
            sacc[nt][3] = __expf(sacc[nt][3] - nm1);
            ps0 += sacc[nt][0] + sacc[nt][1];
            ps1 += sacc[nt][2] + sacc[nt][3];
        }
        ps0 += __shfl_xor_sync(0xffffffffu, ps0, 1);
        ps0 += __shfl_xor_sync(0xffffffffu, ps0, 2);
        ps1 += __shfl_xor_sync(0xffffffffu, ps1, 1);
        ps1 += __shfl_xor_sync(0xffffffffu, ps1, 2);
        run_sum0 = run_sum0 * alpha0 + ps0;
        run_sum1 = run_sum1 * alpha1 + ps1;

#pragma unroll
        for (int nt = 0; nt < 8; nt++) {
            cacc[nt][0] *= alpha0; cacc[nt][1] *= alpha0;
            cacc[nt][2] *= alpha1; cacc[nt][3] *= alpha1;
        }

        // ---- ctx += P @ V (3-pass; P from registers, V^T via ldmatrix.trans)
#pragma unroll
        for (int kk = 0; kk < 4; kk++) {
            uint32_t pah[4], pal[4];
            pah[0] = pack_hl(sacc[2*kk][0],   sacc[2*kk][1],   pal[0]);
            pah[1] = pack_hl(sacc[2*kk][2],   sacc[2*kk][3],   pal[1]);
            pah[2] = pack_hl(sacc[2*kk+1][0], sacc[2*kk+1][1], pal[2]);
            pah[3] = pack_hl(sacc[2*kk+1][2], sacc[2*kk+1][3], pal[3]);
#pragma unroll
            for (int np = 0; np < 4; np++) {
                uint32_t off = (uint32_t)(kk * 16 + (lane & 15)) * ROW2B
                             + np * 32 + ((lane >> 4) << 4);
                uint32_t vh[4], vl[4];
                ldsm_x4_t(vh, sVh + off);
                ldsm_x4_t(vl, sVl + off);
                mma_bf16(cacc[2*np],   pah, vh[0], vh[1]);
                mma_bf16(cacc[2*np],   pal, vh[0], vh[1]);
                mma_bf16(cacc[2*np],   pah, vl[0], vl[1]);
                mma_bf16(cacc[2*np+1], pah, vh[2], vh[3]);
                mma_bf16(cacc[2*np+1], pal, vh[2], vh[3]);
                mma_bf16(cacc[2*np+1], pah, vl[2], vl[3]);
            }
        }
        __syncthreads();
    }

    // ---- final: ctx hi/lo -> g_ctx_h/l [B,S,D] ----
    float inv0 = 1.f / run_sum0;
    float inv1 = 1.f / run_sum1;
    size_t grow0 = (size_t)b * S_ + (q0 + row_l0);
#pragma unroll
    for (int nt = 0; nt < 8; nt++) {
        int col = h * HD_ + nt * 8 + qc2;
        uint32_t lo;
        uint32_t hi = pack_hl(cacc[nt][0] * inv0, cacc[nt][1] * inv0, lo);
        *(uint32_t*)&g_ctx_h[grow0 * D_ + col] = hi;
        *(uint32_t*)&g_ctx_l[grow0 * D_ + col] = lo;
        hi = pack_hl(cacc[nt][2] * inv1, cacc[nt][3] * inv1, lo);
        *(uint32_t*)&g_ctx_h[(grow0 + 8) * D_ + col] = hi;
        *(uint32_t*)&g_ctx_l[(grow0 + 8) * D_ + col] = lo;
    }
}

// ---------------------------------------------------------------------------
extern "C" void kernel_launch(void* const* d_in, const int* in_sizes, int n_in,
                              void* d_out, int out_size)
{
    const float* hidden = (const float*)d_in[0];
    const float* mask   = (const float*)d_in[1];
    const float* at     = (const float*)d_in[2];
    const float* Wq     = (const float*)d_in[3];
    const float* bq     = (const float*)d_in[4];
    const float* Wk     = (const float*)d_in[5];
    const float* bk     = (const float*)d_in[6];
    const float* Wv     = (const float*)d_in[7];
    const float* bv     = (const float*)d_in[8];
    const float* Wo     = (const float*)d_in[9];
    const float* bo     = (const float*)d_in[10];

    float* outp = (float*)d_out;
    const int OUT_ELEMS = 4194304;            // B*S*D
    float* scores = (out_size >= OUT_ELEMS + 1) ? (outp + OUT_ELEMS) : nullptr;

    cudaFuncSetAttribute(gemm_mma, cudaFuncAttributeMaxDynamicSharedMemorySize,
                         GSMEM);
    cudaFuncSetAttribute(attn_mma, cudaFuncAttributeMaxDynamicSharedMemorySize,
                         ASMEM);

    __nv_bfloat16 *hid_h, *hid_l, *ctx_h, *ctx_l, *w_h[4], *w_l[4];
    cudaGetSymbolAddress((void**)&hid_h, g_hid_h);
    cudaGetSymbolAddress((void**)&hid_l, g_hid_l);
    cudaGetSymbolAddress((void**)&ctx_h, g_ctx_h);
    cudaGetSymbolAddress((void**)&ctx_l, g_ctx_l);
    {
        __nv_bfloat16* base_h; __nv_bfloat16* base_l;
        cudaGetSymbolAddress((void**)&base_h, g_w_h);
        cudaGetSymbolAddress((void**)&base_l, g_w_l);
        for (int i = 0; i < 4; i++) {
            w_h[i] = base_h + (size_t)i * D_ * D_;
            w_l[i] = base_l + (size_t)i * D_ * D_;
        }
    }

    // 1) split fp32 -> bf16 hi/lo
    const int n4_hid = M_ * D_ / 4;
    const int n4_w   = D_ * D_ / 4;
    split_kernel<<<(n4_hid + 255)/256, 256>>>(hidden, hid_h, hid_l, n4_hid);
    split_kernel<<<(n4_w   + 255)/256, 256>>>(Wq, w_h[0], w_l[0], n4_w);
    split_kernel<<<(n4_w   + 255)/256, 256>>>(Wk, w_h[1], w_l[1], n4_w);
    split_kernel<<<(n4_w   + 255)/256, 256>>>(Wv, w_h[2], w_l[2], n4_w);
    split_kernel<<<(n4_w   + 255)/256, 256>>>(Wo, w_h[3], w_l[3], n4_w);

    // 2) QKV projections (HMMA)
    dim3 gg(M_/128, D_/128);
    gemm_mma<<<gg, 256, GSMEM>>>(hid_h, hid_l, w_h[0], w_l[0], bq, nullptr, 0);
    gemm_mma<<<gg, 256, GSMEM>>>(hid_h, hid_l, w_h[1], w_l[1], bk, nullptr, 1);
    gemm_mma<<<gg, 256, GSMEM>>>(hid_h, hid_l, w_h[2], w_l[2], bv, nullptr, 2);

    // 3) attention (HMMA flash, 2 CTAs/SM)
    dim3 ga(S_/BQ, B_*NH_);              // 32 x 32
    attn_mma<<<ga, ATHREADS, ASMEM>>>(at, mask, scores);

    // 4) O projection (HMMA)
    gemm_mma<<<gg, 256, GSMEM>>>(ctx_h, ctx_l, w_h[3], w_l[3], bo, outp, 3);
}

// round 10
// speedup vs baseline: 2.6418x; 1.1694x over previous
#include <cuda_runtime.h>
#include <cuda_bf16.h>
#include <cstdint>

// Problem constants
#define B_   2
#define S_   2048
#define D_   1024
#define NH_  16
#define HD_  64
#define M_   (B_*S_)   // 4096

// ---------------------------------------------------------------------------
// Scratch (bf16 hi/lo everywhere)
// ---------------------------------------------------------------------------
__device__ __nv_bfloat16 g_qh[(size_t)B_*NH_*S_*HD_];
__device__ __nv_bfloat16 g_ql[(size_t)B_*NH_*S_*HD_];
__device__ __nv_bfloat16 g_kh[(size_t)B_*NH_*S_*HD_];
__device__ __nv_bfloat16 g_kl[(size_t)B_*NH_*S_*HD_];
__device__ __nv_bfloat16 g_vh[(size_t)B_*NH_*S_*HD_];
__device__ __nv_bfloat16 g_vl[(size_t)B_*NH_*S_*HD_];
__device__ __nv_bfloat16 g_ctx_h[(size_t)M_*D_];
__device__ __nv_bfloat16 g_ctx_l[(size_t)M_*D_];
__device__ __nv_bfloat16 g_hid_h[(size_t)M_*D_];
__device__ __nv_bfloat16 g_hid_l[(size_t)M_*D_];
__device__ __nv_bfloat16 g_w_h[4][(size_t)D_*D_];
__device__ __nv_bfloat16 g_w_l[4][(size_t)D_*D_];

// ---------------------------------------------------------------------------
// helpers
// ---------------------------------------------------------------------------
__device__ __forceinline__ uint32_t cvta_smem(const void* p) {
    uint32_t a;
    asm("{ .reg .u64 t; cvta.to.shared.u64 t, %1; cvt.u32.u64 %0, t; }"
        : "=r"(a) : "l"(p));
    return a;
}
__device__ __forceinline__ void cp_async16(uint32_t s, const void* g) {
    asm volatile("cp.async.cg.shared.global [%0], [%1], 16;"
                 :: "r"(s), "l"(g) : "memory");
}
__device__ __forceinline__ void ldsm_x4(uint32_t (&r)[4], uint32_t addr) {
    asm volatile("ldmatrix.sync.aligned.m8n8.x4.shared.b16 {%0,%1,%2,%3}, [%4];"
                 : "=r"(r[0]), "=r"(r[1]), "=r"(r[2]), "=r"(r[3]) : "r"(addr));
}
__device__ __forceinline__ void ldsm_x4_t(uint32_t (&r)[4], uint32_t addr) {
    asm volatile("ldmatrix.sync.aligned.m8n8.x4.trans.shared.b16 {%0,%1,%2,%3}, [%4];"
                 : "=r"(r[0]), "=r"(r[1]), "=r"(r[2]), "=r"(r[3]) : "r"(addr));
}
__device__ __forceinline__ void mma_bf16(float (&c)[4], const uint32_t (&a)[4],
                                         uint32_t b0, uint32_t b1) {
    asm volatile("mma.sync.aligned.m16n8k16.row.col.f32.bf16.bf16.f32 "
                 "{%0,%1,%2,%3}, {%4,%5,%6,%7}, {%8,%9}, {%0,%1,%2,%3};"
                 : "+f"(c[0]), "+f"(c[1]), "+f"(c[2]), "+f"(c[3])
                 : "r"(a[0]), "r"(a[1]), "r"(a[2]), "r"(a[3]),
                   "r"(b0), "r"(b1));
}
__device__ __forceinline__ uint32_t pack_hl(float x, float y, uint32_t& lo) {
    __nv_bfloat162 h = __floats2bfloat162_rn(x, y);
    float rx = x - __bfloat162float(h.x);
    float ry = y - __bfloat162float(h.y);
    __nv_bfloat162 l = __floats2bfloat162_rn(rx, ry);
    lo = *reinterpret_cast<uint32_t*>(&l);
    return *reinterpret_cast<uint32_t*>(&h);
}

// ---------------------------------------------------------------------------
// fp32 -> bf16 hi/lo split
// ---------------------------------------------------------------------------
__global__ void __launch_bounds__(256)
split_kernel(const float* __restrict__ in, __nv_bfloat16* __restrict__ hi,
             __nv_bfloat16* __restrict__ lo, int n4)
{
    int i = blockIdx.x * blockDim.x + threadIdx.x;
    if (i >= n4) return;
    float4 v = ((const float4*)in)[i];
    uint32_t l0, l1;
    uint32_t h0 = pack_hl(v.x, v.y, l0);
    uint32_t h1 = pack_hl(v.z, v.w, l1);
    ((uint32_t*)hi)[2*i]   = h0;
    ((uint32_t*)hi)[2*i+1] = h1;
    ((uint32_t*)lo)[2*i]   = l0;
    ((uint32_t*)lo)[2*i+1] = l1;
}

// ---------------------------------------------------------------------------
// HMMA split-precision bf16 GEMM (validated R6/R7, unchanged)
// ---------------------------------------------------------------------------
#define KC      32
#define NKC     (D_/KC)
#define AST     40
#define ROWB    (AST*2)
#define TILE_B  (128*ROWB)
#define STAGE_B (4*TILE_B)
#define GSMEM   (2*STAGE_B)

__global__ void __launch_bounds__(256)
gemm_mma(const __nv_bfloat16* __restrict__ Ah, const __nv_bfloat16* __restrict__ Al,
         const __nv_bfloat16* __restrict__ Bh, const __nv_bfloat16* __restrict__ Bl,
         const float* __restrict__ bias, float* __restrict__ outp, int mode)
{
    extern __shared__ unsigned char smem_raw[];
    const uint32_t sbase = cvta_smem(smem_raw);

    const int tid  = threadIdx.x;
    const int wid  = tid >> 5;
    const int lane = tid & 31;
    const int wm   = wid & 3;
    const int wn   = wid >> 2;
    const int bm   = blockIdx.x * 128;
    const int bn   = blockIdx.y * 128;

    const __nv_bfloat16* srcs[4] = { Ah + (size_t)bm * D_, Al + (size_t)bm * D_,
                                     Bh + (size_t)bn * D_, Bl + (size_t)bn * D_ };

    float acc[2][8][4];
#pragma unroll
    for (int mt = 0; mt < 2; mt++)
#pragma unroll
        for (int nt = 0; nt < 8; nt++)
#pragma unroll
            for (int i = 0; i < 4; i++) acc[mt][nt][i] = 0.f;

#define LOAD_STAGE(kc, stg)                                                   \
    do {                                                                      \
        uint32_t sb_ = sbase + (stg) * STAGE_B;                               \
        int k0_ = (kc) * KC;                                                  \
        _Pragma("unroll")                                                     \
        for (int it = 0; it < 8; it++) {                                      \
            int idx  = tid + it * 256;                                        \
            int tile = idx >> 9;                                              \
            int rem  = idx & 511;                                             \
            int row  = rem >> 2;                                              \
            int q    = rem & 3;                                               \
            cp_async16(sb_ + tile * TILE_B + row * ROWB + q * 16,             \
                       srcs[tile] + (size_t)row * D_ + k0_ + q * 8);          \
        }                                                                     \
        asm volatile("cp.async.commit_group;" ::: "memory");                  \
    } while (0)

    LOAD_STAGE(0, 0);

    for (int kc = 0; kc < NKC; kc++) {
        if (kc + 1 < NKC) {
            LOAD_STAGE(kc + 1, (kc + 1) & 1);
            asm volatile("cp.async.wait_group 1;" ::: "memory");
        } else {
            asm volatile("cp.async.wait_group 0;" ::: "memory");
        }
        __syncthreads();

        const uint32_t st = sbase + (kc & 1) * STAGE_B;
        const uint32_t sAh = st + 0 * TILE_B;
        const uint32_t sAl = st + 1 * TILE_B;
        const uint32_t sBh = st + 2 * TILE_B;
        const uint32_t sBl = st + 3 * TILE_B;

#pragma unroll
        for (int ks = 0; ks < 2; ks++) {
            const int kofs = ks * 16;
            uint32_t ah[2][4], al[2][4];
            {
                int arow = wm * 32 + (lane & 15);
                int acol = ((lane >> 4) << 3) + kofs;
#pragma unroll
                for (int mt = 0; mt < 2; mt++) {
                    uint32_t off = (uint32_t)(arow + mt * 16) * ROWB + acol * 2;
                    ldsm_x4(ah[mt], sAh + off);
                    ldsm_x4(al[mt], sAl + off);
                }
            }
            uint32_t bh[8][2], bl[8][2];
            {
                int brow = wn * 64 + ((lane >> 4) << 3) + (lane & 7);
                int bcol = (((lane >> 3) & 1) << 3) + kofs;
#pragma unroll
                for (int p = 0; p < 4; p++) {
                    uint32_t off = (uint32_t)(brow + p * 16) * ROWB + bcol * 2;
                    uint32_t r[4];
                    ldsm_x4(r, sBh + off);
                    bh[2*p][0] = r[0]; bh[2*p][1] = r[1];
                    bh[2*p+1][0] = r[2]; bh[2*p+1][1] = r[3];
                    ldsm_x4(r, sBl + off);
                    bl[2*p][0] = r[0]; bl[2*p][1] = r[1];
                    bl[2*p+1][0] = r[2]; bl[2*p+1][1] = r[3];
                }
            }
#pragma unroll
            for (int mt = 0; mt < 2; mt++)
#pragma unroll
                for (int nt = 0; nt < 8; nt++) {
                    mma_bf16(acc[mt][nt], ah[mt], bh[nt][0], bh[nt][1]);
                    mma_bf16(acc[mt][nt], ah[mt], bl[nt][0], bl[nt][1]);
                    mma_bf16(acc[mt][nt], al[mt], bh[nt][0], bh[nt][1]);
                }
        }
        __syncthreads();
    }

    const int qr = lane >> 2;
    const int qc = (lane & 3) * 2;
    __nv_bfloat16* oh = (mode == 0) ? g_qh : (mode == 1) ? g_kh : g_vh;
    __nv_bfloat16* ol = (mode == 0) ? g_ql : (mode == 1) ? g_kl : g_vl;

#pragma unroll
    for (int mt = 0; mt < 2; mt++) {
#pragma unroll
        for (int half = 0; half < 2; half++) {
            int m = bm + wm * 32 + mt * 16 + qr + half * 8;
            int b = m >> 11;
            int s = m & (S_ - 1);
#pragma unroll
            for (int nt = 0; nt < 8; nt++) {
                int n = bn + wn * 64 + nt * 8 + qc;
                float ox = acc[mt][nt][2*half + 0] + bias[n + 0];
                float oy = acc[mt][nt][2*half + 1] + bias[n + 1];
                if (mode == 3) {
                    float2 o = make_float2(ox, oy);
                    *(float2*)&outp[(size_t)m * D_ + n] = o;
                } else {
                    int h  = n >> 6;
                    int hd = n & 63;
                    size_t off = ((size_t)((b*NH_ + h)*S_ + s))*HD_ + hd;
                    uint32_t lo;
                    uint32_t hi = pack_hl(ox, oy, lo);
                    *(uint32_t*)&oh[off] = hi;
                    *(uint32_t*)&ol[off] = lo;
                }
            }
        }
    }
}

// ---------------------------------------------------------------------------
// HMMA flash attention. R9: BQ=128, 4 warps x 32 rows (2 m16 tiles/warp),
// 128 threads, 108KB smem -> 2 CTAs/SM. K/V fragments shared across both
// m-tiles -> ldmatrix traffic per MMA drops 1.8x (attacking the L1TEX bind).
// ---------------------------------------------------------------------------
#define BQ      128
#define ATHREADS 128
#define BKV     64
#define AST2    72
#define ROW2B   (AST2*2)
#define QTILE_B (BQ*ROW2B)                // 18432
#define KVT_B   (BKV*ROW2B)               // 9216
#define KVSTG_B (4*KVT_B)                 // 36864
#define ASMEM   (2*QTILE_B + 2*KVSTG_B)   // 110592

__global__ void __launch_bounds__(ATHREADS)
attn_mma(const float* __restrict__ at, const float* __restrict__ mask,
         float* __restrict__ scores)
{
    extern __shared__ unsigned char smem_raw[];
    const uint32_t sbase = cvta_smem(smem_raw);

    const int tid  = threadIdx.x;
    const int wid  = tid >> 5;
    const int lane = tid & 31;
    const int bh   = blockIdx.y;
    const int b    = bh >> 4;
    const int h    = bh & 15;
    const int q0   = blockIdx.x * BQ;

    const __nv_bfloat16* qh = g_qh + (size_t)bh * S_ * HD_;
    const __nv_bfloat16* ql = g_ql + (size_t)bh * S_ * HD_;
    const __nv_bfloat16* kv_srcs[4] = {
        g_kh + (size_t)bh * S_ * HD_, g_kl + (size_t)bh * S_ * HD_,
        g_vh + (size_t)bh * S_ * HD_, g_vl + (size_t)bh * S_ * HD_ };

    // ---- load Q hi/lo (128 x 64) into smem: 2048 16B chunks, 16/thread ----
#pragma unroll
    for (int it = 0; it < 16; it++) {
        int idx  = tid + it * ATHREADS;      // 0..2047
        int half = idx >> 10;
        int rem  = idx & 1023;
        int row  = rem >> 3;
        int c    = rem & 7;
        const __nv_bfloat16* src = (half ? ql : qh) + (size_t)(q0 + row) * HD_ + c * 8;
        *(uint4*)(smem_raw + half * QTILE_B + row * ROW2B + c * 16) =
            *(const uint4*)src;
    }

    float cacc[2][8][4];
#pragma unroll
    for (int mt = 0; mt < 2; mt++)
#pragma unroll
        for (int nt = 0; nt < 8; nt++)
#pragma unroll
            for (int i = 0; i < 4; i++) cacc[mt][nt][i] = 0.f;
    float run_max[2][2], run_sum[2][2];
#pragma unroll
    for (int mt = 0; mt < 2; mt++) {
        run_max[mt][0] = -1e30f; run_max[mt][1] = -1e30f;
        run_sum[mt][0] = 0.f;    run_sum[mt][1] = 0.f;
    }

    const int qr  = lane >> 2;
    const int qc2 = (lane & 3) * 2;

#define KV_LOAD(jt, stg)                                                      \
    do {                                                                      \
        uint32_t sb_ = sbase + 2*QTILE_B + (stg) * KVSTG_B;                   \
        int r0_ = (jt) * BKV;                                                 \
        _Pragma("unroll")                                                     \
        for (int it = 0; it < 16; it++) {                                     \
            int idx  = tid + it * ATHREADS;                                   \
            int tile = idx >> 9;                                              \
            int rem  = idx & 511;                                             \
            int row  = rem >> 3;                                              \
            int c    = rem & 7;                                               \
            cp_async16(sb_ + tile * KVT_B + row * ROW2B + c * 16,             \
                       kv_srcs[tile] + (size_t)(r0_ + row) * HD_ + c * 8);    \
        }                                                                     \
        asm volatile("cp.async.commit_group;" ::: "memory");                  \
    } while (0)

    KV_LOAD(0, 0);

    const float scale = 0.125f;

    for (int j = 0; j < S_/BKV; j++) {
        if (j + 1 < S_/BKV) {
            KV_LOAD(j + 1, (j + 1) & 1);
            asm volatile("cp.async.wait_group 1;" ::: "memory");
        } else {
            asm volatile("cp.async.wait_group 0;" ::: "memory");
        }
        __syncthreads();

        const uint32_t st  = sbase + 2*QTILE_B + (j & 1) * KVSTG_B;
        const uint32_t sKh = st + 0 * KVT_B;
        const uint32_t sKl = st + 1 * KVT_B;
        const uint32_t sVh = st + 2 * KVT_B;
        const uint32_t sVl = st + 3 * KVT_B;

        // ---- S = Q @ K^T (3-pass), 2 m-tiles per warp, K frags shared ----
        float sacc[2][8][4];
#pragma unroll
        for (int mt = 0; mt < 2; mt++)
#pragma unroll
            for (int nt = 0; nt < 8; nt++)
#pragma unroll
                for (int i = 0; i < 4; i++) sacc[mt][nt][i] = 0.f;

#pragma unroll
        for (int ks = 0; ks < 4; ks++) {
            uint32_t qhf[2][4], qlf[2][4];
#pragma unroll
            for (int mt = 0; mt < 2; mt++) {
                uint32_t off = (uint32_t)(wid * 32 + mt * 16 + (lane & 15)) * ROW2B
                             + ks * 32 + ((lane >> 4) << 4);
                ldsm_x4(qhf[mt], sbase + off);
                ldsm_x4(qlf[mt], sbase + QTILE_B + off);
            }
#pragma unroll
            for (int np = 0; np < 4; np++) {
                int brow = np * 16 + ((lane >> 4) << 3) + (lane & 7);
                uint32_t off = (uint32_t)brow * ROW2B
                             + (((lane >> 3) & 1) << 4) + ks * 32;
                uint32_t rh[4], rl[4];
                ldsm_x4(rh, sKh + off);
                ldsm_x4(rl, sKl + off);
#pragma unroll
                for (int mt = 0; mt < 2; mt++) {
                    mma_bf16(sacc[mt][2*np],   qhf[mt], rh[0], rh[1]);
                    mma_bf16(sacc[mt][2*np],   qhf[mt], rl[0], rl[1]);
                    mma_bf16(sacc[mt][2*np],   qlf[mt], rh[0], rh[1]);
                    mma_bf16(sacc[mt][2*np+1], qhf[mt], rh[2], rh[3]);
                    mma_bf16(sacc[mt][2*np+1], qhf[mt], rl[2], rl[3]);
                    mma_bf16(sacc[mt][2*np+1], qlf[mt], rh[2], rh[3]);
                }
            }
        }

        // ---- epilogue per m-tile: scale + at + mask, scores, softmax ----
        const int j0 = j * BKV;
#pragma unroll
        for (int mt = 0; mt < 2; mt++) {
            const int row_l0 = wid * 32 + mt * 16 + qr;
            float rm0 = -1e30f, rm1 = -1e30f;
#pragma unroll
            for (int nt = 0; nt < 8; nt++) {
                int col = j0 + nt * 8 + qc2;
                float2 mk = *(const float2*)&mask[(size_t)b * S_ + col];
                size_t off0 = ((size_t)bh * S_ + (size_t)(q0 + row_l0)) * S_ + col;
                size_t off1 = off0 + (size_t)8 * S_;
                float2 a0 = *(const float2*)&at[off0];
                float2 a1 = *(const float2*)&at[off1];
                sacc[mt][nt][0] = fmaf(sacc[mt][nt][0], scale, a0.x) + mk.x;
                sacc[mt][nt][1] = fmaf(sacc[mt][nt][1], scale, a0.y) + mk.y;
                sacc[mt][nt][2] = fmaf(sacc[mt][nt][2], scale, a1.x) + mk.x;
                sacc[mt][nt][3] = fmaf(sacc[mt][nt][3], scale, a1.y) + mk.y;
                *(float2*)&scores[off0] = make_float2(sacc[mt][nt][0], sacc[mt][nt][1]);
                *(float2*)&scores[off1] = make_float2(sacc[mt][nt][2], sacc[mt][nt][3]);
                rm0 = fmaxf(rm0, fmaxf(sacc[mt][nt][0], sacc[mt][nt][1]));
                rm1 = fmaxf(rm1, fmaxf(sacc[mt][nt][2], sacc[mt][nt][3]));
            }
            rm0 = fmaxf(rm0, __shfl_xor_sync(0xffffffffu, rm0, 1));
            rm0 = fmaxf(rm0, __shfl_xor_sync(0xffffffffu, rm0, 2));
            rm1 = fmaxf(rm1, __shfl_xor_sync(0xffffffffu, rm1, 1));
            rm1 = fmaxf(rm1, __shfl_xor_sync(0xffffffffu, rm1, 2));

            float nm0 = fmaxf(run_max[mt][0], rm0);
            float nm1 = fmaxf(run_max[mt][1], rm1);
            float alpha0 = __expf(run_max[mt][0] - nm0);
            float alpha1 = __expf(run_max[mt][1] - nm1);
            run_max[mt][0] = nm0; run_max[mt][1] = nm1;

            float ps0 = 0.f, ps1 = 0.f;
#pragma unroll
            for (int nt = 0; nt < 8; nt++) {
                sacc[mt][nt][0] = __expf(sacc[mt][nt][0] - nm0);
                sacc[mt][nt][1] = __expf(sacc[mt][nt][1] - nm0);
                sacc[mt][nt][2] = __expf(sacc[mt][nt][2] - nm1);
                sacc[mt][nt][3] = __expf(sacc[mt][nt][3] - nm1);
                ps0 += sacc[mt][nt][0] + sacc[mt][nt][1];
                ps1 += sacc[mt][nt][2] + sacc[mt][nt][3];
            }
            ps0 += __shfl_xor_sync(0xffffffffu, ps0, 1);
            ps0 += __shfl_xor_sync(0xffffffffu, ps0, 2);
            ps1 += __shfl_xor_sync(0xffffffffu, ps1, 1);
            ps1 += __shfl_xor_sync(0xffffffffu, ps1, 2);
            run_sum[mt][0] = run_sum[mt][0] * alpha0 + ps0;
            run_sum[mt][1] = run_sum[mt][1] * alpha1 + ps1;

#pragma unroll
            for (int nt = 0; nt < 8; nt++) {
                cacc[mt][nt][0] *= alpha0; cacc[mt][nt][1] *= alpha0;
                cacc[mt][nt][2] *= alpha1; cacc[mt][nt][3] *= alpha1;
            }
        }

        // ---- ctx += P @ V (3-pass); V frags shared across both m-tiles ----
#pragma unroll
        for (int kk = 0; kk < 4; kk++) {
            uint32_t pah[2][4], pal[2][4];
#pragma unroll
            for (int mt = 0; mt < 2; mt++) {
                pah[mt][0] = pack_hl(sacc[mt][2*kk][0],   sacc[mt][2*kk][1],   pal[mt][0]);
                pah[mt][1] = pack_hl(sacc[mt][2*kk][2],   sacc[mt][2*kk][3],   pal[mt][1]);
                pah[mt][2] = pack_hl(sacc[mt][2*kk+1][0], sacc[mt][2*kk+1][1], pal[mt][2]);
                pah[mt][3] = pack_hl(sacc[mt][2*kk+1][2], sacc[mt][2*kk+1][3], pal[mt][3]);
            }
#pragma unroll
            for (int np = 0; np < 4; np++) {
                uint32_t off = (uint32_t)(kk * 16 + (lane & 15)) * ROW2B
                             + np * 32 + ((lane >> 4) << 4);
                uint32_t vh[4], vl[4];
                ldsm_x4_t(vh, sVh + off);
                ldsm_x4_t(vl, sVl + off);
#pragma unroll
                for (int mt = 0; mt < 2; mt++) {
                    mma_bf16(cacc[mt][2*np],   pah[mt], vh[0], vh[1]);
                    mma_bf16(cacc[mt][2*np],   pal[mt], vh[0], vh[1]);
                    mma_bf16(cacc[mt][2*np],   pah[mt], vl[0], vl[1]);
                    mma_bf16(cacc[mt][2*np+1], pah[mt], vh[2], vh[3]);
                    mma_bf16(cacc[mt][2*np+1], pal[mt], vh[2], vh[3]);
                    mma_bf16(cacc[mt][2*np+1], pah[mt], vl[2], vl[3]);
                }
            }
        }
        __syncthreads();
    }

    // ---- final: ctx hi/lo -> g_ctx_h/l [B,S,D] ----
#pragma unroll
    for (int mt = 0; mt < 2; mt++) {
        float inv0 = 1.f / run_sum[mt][0];
        float inv1 = 1.f / run_sum[mt][1];
        size_t grow0 = (size_t)b * S_ + (q0 + wid * 32 + mt * 16 + qr);
#pragma unroll
        for (int nt = 0; nt < 8; nt++) {
            int col = h * HD_ + nt * 8 + qc2;
            uint32_t lo;
            uint32_t hi = pack_hl(cacc[mt][nt][0] * inv0, cacc[mt][nt][1] * inv0, lo);
            *(uint32_t*)&g_ctx_h[grow0 * D_ + col] = hi;
            *(uint32_t*)&g_ctx_l[grow0 * D_ + col] = lo;
            hi = pack_hl(cacc[mt][nt][2] * inv1, cacc[mt][nt][3] * inv1, lo);
            *(uint32_t*)&g_ctx_h[(grow0 + 8) * D_ + col] = hi;
            *(uint32_t*)&g_ctx_l[(grow0 + 8) * D_ + col] = lo;
        }
    }
}

// ---------------------------------------------------------------------------
extern "C" void kernel_launch(void* const* d_in, const int* in_sizes, int n_in,
                              void* d_out, int out_size)
{
    const float* hidden = (const float*)d_in[0];
    const float* mask   = (const float*)d_in[1];
    const float* at     = (const float*)d_in[2];
    const float* Wq     = (const float*)d_in[3];
    const float* bq     = (const float*)d_in[4];
    const float* Wk     = (const float*)d_in[5];
    const float* bk     = (const float*)d_in[6];
    const float* Wv     = (const float*)d_in[7];
    const float* bv     = (const float*)d_in[8];
    const float* Wo     = (const float*)d_in[9];
    const float* bo     = (const float*)d_in[10];

    float* outp = (float*)d_out;
    const int OUT_ELEMS = 4194304;            // B*S*D
    float* scores = (out_size >= OUT_ELEMS + 1) ? (outp + OUT_ELEMS) : nullptr;

    cudaFuncSetAttribute(gemm_mma, cudaFuncAttributeMaxDynamicSharedMemorySize,
                         GSMEM);
    cudaFuncSetAttribute(attn_mma, cudaFuncAttributeMaxDynamicSharedMemorySize,
                         ASMEM);

    __nv_bfloat16 *hid_h, *hid_l, *ctx_h, *ctx_l, *w_h[4], *w_l[4];
    cudaGetSymbolAddress((void**)&hid_h, g_hid_h);
    cudaGetSymbolAddress((void**)&hid_l, g_hid_l);
    cudaGetSymbolAddress((void**)&ctx_h, g_ctx_h);
    cudaGetSymbolAddress((void**)&ctx_l, g_ctx_l);
    {
        __nv_bfloat16* base_h; __nv_bfloat16* base_l;
        cudaGetSymbolAddress((void**)&base_h, g_w_h);
        cudaGetSymbolAddress((void**)&base_l, g_w_l);
        for (int i = 0; i < 4; i++) {
            w_h[i] = base_h + (size_t)i * D_ * D_;
            w_l[i] = base_l + (size_t)i * D_ * D_;
        }
    }

    // 1) split fp32 -> bf16 hi/lo
    const int n4_hid = M_ * D_ / 4;
    const int n4_w   = D_ * D_ / 4;
    split_kernel<<<(n4_hid + 255)/256, 256>>>(hidden, hid_h, hid_l, n4_hid);
    split_kernel<<<(n4_w   + 255)/256, 256>>>(Wq, w_h[0], w_l[0], n4_w);
    split_kernel<<<(n4_w   + 255)/256, 256>>>(Wk, w_h[1], w_l[1], n4_w);
    split_kernel<<<(n4_w   + 255)/256, 256>>>(Wv, w_h[2], w_l[2], n4_w);
    split_kernel<<<(n4_w   + 255)/256, 256>>>(Wo, w_h[3], w_l[3], n4_w);

    // 2) QKV projections (HMMA)
    dim3 gg(M_/128, D_/128);
    gemm_mma<<<gg, 256, GSMEM>>>(hid_h, hid_l, w_h[0], w_l[0], bq, nullptr, 0);
    gemm_mma<<<gg, 256, GSMEM>>>(hid_h, hid_l, w_h[1], w_l[1], bk, nullptr, 1);
    gemm_mma<<<gg, 256, GSMEM>>>(hid_h, hid_l, w_h[2], w_l[2], bv, nullptr, 2);

    // 3) attention (HMMA flash, 32 rows/warp)
    dim3 ga(S_/BQ, B_*NH_);              // 16 x 32
    attn_mma<<<ga, ATHREADS, ASMEM>>>(at, mask, scores);

    // 4) O projection (HMMA)
    gemm_mma<<<gg, 256, GSMEM>>>(ctx_h, ctx_l, w_h[3], w_l[3], bo, outp, 3);
}